// round 1
// baseline (speedup 1.0000x reference)
#include <cuda_runtime.h>
#include <cuda_bf16.h>
#include <math.h>

// ---------------- model constants ----------------
#define TT 2048      // B*S tokens
#define BB 2
#define SS 1024
#define DD 1024
#define HH 16
#define KVH 4
#define HDIM 64
#define LL 4
#define EE 8
#define FF 1024
#define VV 32000
#define CAP 4096     // max pairs per expert (<= 2*TT)
#define QD (HH*HDIM)   // 1024
#define KD (KVH*HDIM)  // 256
#define ATT_SCALE 0.125f
#define RMS_EPS 1e-6f

// ---------------- scratch (device globals; no allocation allowed) ----------------
__device__ float g_x[TT*DD];
__device__ float g_h[TT*DD];
__device__ float g_q[TT*QD];
__device__ float g_k[TT*KD];
__device__ float g_v[TT*KD];
__device__ float g_scores[(long)BB*HH*SS*SS];   // 134 MB
__device__ float g_o[TT*QD];
__device__ float g_gate[2*TT*FF];
__device__ float g_up[2*TT*FF];
__device__ float g_y[2*TT*DD];
__device__ float g_rlog[TT*EE];
__device__ float g_pairw[2*TT];
__device__ int   g_cnt[EE];
__device__ int   g_ptok[EE*CAP];
__device__ int   g_ppair[EE*CAP];

// ---------------- helpers ----------------
__device__ __forceinline__ float warpReduceSum(float v){
#pragma unroll
    for (int o = 16; o; o >>= 1) v += __shfl_xor_sync(0xffffffffu, v, o);
    return v;
}

// ---------------- GEMM tile body: 128x128x8, 256 threads, 8x8 micro ----------------
constexpr int BM = 128, BN = 128, BK = 8;

template<bool TB, bool ADD>
__device__ __forceinline__ void gemm_body(
    const float* __restrict__ A, const float* __restrict__ B, float* __restrict__ C,
    int M, int N, int K, int lda, int ldb, int ldc,
    int m0, int n0, float alpha,
    const int* __restrict__ aidx, const int* __restrict__ cidx)
{
    __shared__ float As[BK][BM+4];
    __shared__ float Bs[BK][BN+4];
    const int tid = threadIdx.x;
    const int tx = tid & 15, ty = tid >> 4;
    float acc[8][8];
#pragma unroll
    for (int i = 0; i < 8; i++)
#pragma unroll
        for (int j = 0; j < 8; j++) acc[i][j] = 0.f;

    // A tile load mapping: 128 rows x 8 k, each thread one float4 along k
    const int arow = tid >> 1;
    const int aseg = (tid & 1) * 4;
    const bool a_ok = (m0 + arow) < M;
    long a_off = 0;
    if (a_ok) {
        int r = aidx ? aidx[m0 + arow] : (m0 + arow);
        a_off = (long)r * lda;
    }

    // B tile load mapping
    int b_k = 0, b_n = 0, b_seg = 0;
    long b_off = 0;
    bool b_ok = false;
    if (!TB) {
        b_k = tid >> 5;               // 0..7
        b_n = (tid & 31) * 4;         // 0..124
        b_ok = (n0 + b_n) < N;        // N % 4 == 0 for all uses
        b_off = (long)b_k * ldb + n0 + b_n;
    } else {
        b_n = tid >> 1;               // 0..127 (n row of B[N,K])
        b_seg = (tid & 1) * 4;
        b_ok = (n0 + b_n) < N;
        b_off = (long)(n0 + b_n) * ldb + b_seg;
    }

    for (int kb = 0; kb < K; kb += BK) {
        float4 av = make_float4(0.f, 0.f, 0.f, 0.f);
        if (a_ok) av = *reinterpret_cast<const float4*>(A + a_off + kb + aseg);
        As[aseg+0][arow] = av.x; As[aseg+1][arow] = av.y;
        As[aseg+2][arow] = av.z; As[aseg+3][arow] = av.w;

        if (!TB) {
            float4 bv = make_float4(0.f, 0.f, 0.f, 0.f);
            if (b_ok) bv = *reinterpret_cast<const float4*>(B + b_off + (long)kb * ldb);
            *reinterpret_cast<float4*>(&Bs[b_k][b_n]) = bv;
        } else {
            float4 bv = make_float4(0.f, 0.f, 0.f, 0.f);
            if (b_ok) bv = *reinterpret_cast<const float4*>(B + b_off + kb);
            Bs[b_seg+0][b_n] = bv.x; Bs[b_seg+1][b_n] = bv.y;
            Bs[b_seg+2][b_n] = bv.z; Bs[b_seg+3][b_n] = bv.w;
        }
        __syncthreads();
#pragma unroll
        for (int kk = 0; kk < BK; kk++) {
            float a[8], b[8];
            *reinterpret_cast<float4*>(&a[0]) = *reinterpret_cast<const float4*>(&As[kk][ty*8]);
            *reinterpret_cast<float4*>(&a[4]) = *reinterpret_cast<const float4*>(&As[kk][ty*8+4]);
            *reinterpret_cast<float4*>(&b[0]) = *reinterpret_cast<const float4*>(&Bs[kk][tx*8]);
            *reinterpret_cast<float4*>(&b[4]) = *reinterpret_cast<const float4*>(&Bs[kk][tx*8+4]);
#pragma unroll
            for (int i = 0; i < 8; i++)
#pragma unroll
                for (int j = 0; j < 8; j++) acc[i][j] = fmaf(a[i], b[j], acc[i][j]);
        }
        __syncthreads();
    }

#pragma unroll
    for (int i = 0; i < 8; i++) {
        int m = m0 + ty*8 + i;
        if (m >= M) continue;
        long crow = cidx ? (long)cidx[m] : (long)m;
        float* cp = C + crow * ldc;
#pragma unroll
        for (int j = 0; j < 8; j++) {
            int n = n0 + tx*8 + j;
            if (n < N) {
                float vv = acc[i][j] * alpha;
                if (ADD) cp[n] += vv; else cp[n] = vv;
            }
        }
    }
}

template<bool TB, bool ADD>
__global__ void __launch_bounds__(256)
gemm_kernel(const float* __restrict__ A, const float* __restrict__ B, float* __restrict__ C,
            int M, int N, int K, int lda, int ldb, int ldc)
{
    gemm_body<TB, ADD>(A, B, C, M, N, K, lda, ldb, ldc,
                       blockIdx.y * BM, blockIdx.x * BN, 1.f, nullptr, nullptr);
}

__global__ void __launch_bounds__(256)
moe_gemm_kernel(const float* __restrict__ A, const float* __restrict__ Bbase, long bstride,
                float* __restrict__ C, int N, int K, int lda, int ldb, int ldc,
                const int* __restrict__ aidx, const int* __restrict__ cidx,
                const int* __restrict__ cnt)
{
    int e = blockIdx.z;
    int M = cnt[e];
    int m0 = blockIdx.y * BM;
    if (m0 >= M) return;
    gemm_body<false, false>(A, Bbase + (long)e * bstride, C, M, N, K, lda, ldb, ldc,
                            m0, blockIdx.x * BN, 1.f, aidx + e * CAP, cidx + e * CAP);
}

__global__ void __launch_bounds__(256)
attn_scores_kernel(const float* __restrict__ q, const float* __restrict__ k,
                   float* __restrict__ scores)
{
    int z = blockIdx.z;
    int b = z / HH, h = z % HH;
    int m0 = blockIdx.y * BM, n0 = blockIdx.x * BN;
    if (n0 >= m0 + BM) return;   // fully masked tile (causal)
    const float* A = q + (long)b * SS * QD + h * HDIM;
    const float* B = k + (long)b * SS * KD + (h >> 2) * HDIM;
    float* C = scores + (long)z * SS * SS;
    gemm_body<true, false>(A, B, C, SS, SS, HDIM, QD, KD, SS, m0, n0, ATT_SCALE,
                           nullptr, nullptr);
}

__global__ void __launch_bounds__(256)
attn_pv_kernel(const float* __restrict__ scores, const float* __restrict__ v,
               float* __restrict__ o)
{
    int z = blockIdx.z;
    int b = z / HH, h = z % HH;
    const float* A = scores + (long)z * SS * SS;
    const float* B = v + (long)b * SS * KD + (h >> 2) * HDIM;
    float* C = o + (long)b * SS * QD + h * HDIM;
    gemm_body<false, false>(A, B, C, SS, HDIM, SS, SS, KD, QD,
                            blockIdx.y * BM, 0, 1.f, nullptr, nullptr);
}

// ---------------- elementwise / small kernels ----------------
__global__ void embed_kernel(const int* __restrict__ ids, const float* __restrict__ emb,
                             float* __restrict__ x)
{
    int t = blockIdx.x;
    long src = (long)ids[t] * DD;
    int d = threadIdx.x * 4;
    *reinterpret_cast<float4*>(x + (long)t * DD + d) =
        *reinterpret_cast<const float4*>(emb + src + d);
}

__global__ void rmsnorm_kernel(const float* __restrict__ in, const float* __restrict__ w,
                               float* __restrict__ out)
{
    int t = blockIdx.x;
    const float* row = in + (long)t * DD;
    int d = threadIdx.x * 4;
    float4 va = *reinterpret_cast<const float4*>(row + d);
    float ss = va.x*va.x + va.y*va.y + va.z*va.z + va.w*va.w;
    __shared__ float red[8];
    __shared__ float bc;
    ss = warpReduceSum(ss);
    if ((threadIdx.x & 31) == 0) red[threadIdx.x >> 5] = ss;
    __syncthreads();
    if (threadIdx.x == 0) {
        float s = 0.f;
#pragma unroll
        for (int i = 0; i < 8; i++) s += red[i];
        bc = rsqrtf(s / (float)DD + RMS_EPS);
    }
    __syncthreads();
    float r = bc;
    float4 wv = *reinterpret_cast<const float4*>(w + d);
    float4 ov;
    ov.x = va.x * r * wv.x; ov.y = va.y * r * wv.y;
    ov.z = va.z * r * wv.z; ov.w = va.w * r * wv.w;
    *reinterpret_cast<float4*>(out + (long)t * DD + d) = ov;
}

// per-head RMS norm + RoPE (in place). one warp per (token, head)
__global__ void qk_rope_kernel(float* __restrict__ buf, const float* __restrict__ nw,
                               const int* __restrict__ pos_ids, int nheads, int rowstride)
{
    int gw = (blockIdx.x * blockDim.x + threadIdx.x) >> 5;
    int lane = threadIdx.x & 31;
    int t = gw / nheads;
    int hh = gw - t * nheads;
    if (t >= TT) return;
    float* p = buf + (long)t * rowstride + hh * HDIM;
    float v0 = p[lane], v1 = p[lane + 32];
    float ss = warpReduceSum(v0 * v0 + v1 * v1);
    float r = rsqrtf(ss / 64.f + RMS_EPS);
    v0 *= r * nw[lane];
    v1 *= r * nw[lane + 32];
    float inv_freq = (float)pow(1000000.0, -(double)lane / 32.0);
    float ang = (float)pos_ids[t] * inv_freq;
    float c, s;
    sincosf(ang, &s, &c);
    p[lane]      = v0 * c - v1 * s;
    p[lane + 32] = v1 * c + v0 * s;
}

__global__ void softmax_kernel(float* __restrict__ scores)
{
    long z = blockIdx.y;
    int i = blockIdx.x;
    float* row = scores + (z * SS + i) * (long)SS;
    int valid = i + 1;
    __shared__ float red[8];
    __shared__ float bc;
    float m = -1e30f;
    for (int j = threadIdx.x; j < valid; j += 256) m = fmaxf(m, row[j]);
#pragma unroll
    for (int o = 16; o; o >>= 1) m = fmaxf(m, __shfl_xor_sync(0xffffffffu, m, o));
    if ((threadIdx.x & 31) == 0) red[threadIdx.x >> 5] = m;
    __syncthreads();
    if (threadIdx.x == 0) {
        float mm = -1e30f;
#pragma unroll
        for (int i2 = 0; i2 < 8; i2++) mm = fmaxf(mm, red[i2]);
        bc = mm;
    }
    __syncthreads();
    m = bc;
    float s = 0.f;
    for (int j = threadIdx.x; j < valid; j += 256) s += expf(row[j] - m);
    s = warpReduceSum(s);
    if ((threadIdx.x & 31) == 0) red[threadIdx.x >> 5] = s;
    __syncthreads();
    if (threadIdx.x == 0) {
        float t = 0.f;
#pragma unroll
        for (int i2 = 0; i2 < 8; i2++) t += red[i2];
        bc = t;
    }
    __syncthreads();
    float inv = 1.f / bc;
    for (int j = threadIdx.x; j < valid; j += 256) row[j] = expf(row[j] - m) * inv;
    for (int j = valid + threadIdx.x; j < SS; j += 256) row[j] = 0.f;
}

__global__ void router_kernel(const float* __restrict__ h, const float* __restrict__ rw,
                              float* __restrict__ lg)
{
    int t = blockIdx.x;
    __shared__ float sh[DD];
    for (int d = threadIdx.x; d < DD; d += 256) sh[d] = h[(long)t * DD + d];
    __syncthreads();
    int w = threadIdx.x >> 5, lane = threadIdx.x & 31;
    float s = 0.f;
    for (int d = lane; d < DD; d += 32) s += sh[d] * rw[d * EE + w];
    s = warpReduceSum(s);
    if (lane == 0) lg[t * EE + w] = s;
}

__global__ void assign_kernel(const float* __restrict__ lg, int* __restrict__ cnt,
                              int* __restrict__ ptok, int* __restrict__ ppair,
                              float* __restrict__ pw)
{
    int t = blockIdx.x * blockDim.x + threadIdx.x;
    if (t >= TT) return;
    float l1 = -1e30f, l2 = -1e30f;
    int i1 = 0, i2 = 0;
#pragma unroll
    for (int e = 0; e < EE; e++) {
        float v = lg[t * EE + e];
        if (v > l1) { l2 = l1; i2 = i1; l1 = v; i1 = e; }
        else if (v > l2) { l2 = v; i2 = e; }
    }
    float e2 = expf(l2 - l1);
    float w1 = 1.f / (1.f + e2);
    float w2 = e2 / (1.f + e2);
    int p = atomicAdd(&cnt[i1], 1);
    ptok[i1 * CAP + p] = t;  ppair[i1 * CAP + p] = 2 * t;
    p = atomicAdd(&cnt[i2], 1);
    ptok[i2 * CAP + p] = t;  ppair[i2 * CAP + p] = 2 * t + 1;
    pw[2 * t] = w1;  pw[2 * t + 1] = w2;
}

__global__ void silu_mul_kernel(float* __restrict__ g, const float* __restrict__ u)
{
    long i = (long)blockIdx.x * blockDim.x + threadIdx.x;
    float gv = g[i];
    float sg = gv / (1.f + expf(-gv));
    g[i] = sg * u[i];
}

__global__ void combine_kernel(float* __restrict__ x, const float* __restrict__ y,
                               const float* __restrict__ pw)
{
    int t = blockIdx.x;
    float w0 = pw[2 * t], w1 = pw[2 * t + 1];
    int d = threadIdx.x * 4;
    float4 a  = *reinterpret_cast<float4*>(x + (long)t * DD + d);
    float4 y0 = *reinterpret_cast<const float4*>(y + (long)(2 * t) * DD + d);
    float4 y1 = *reinterpret_cast<const float4*>(y + (long)(2 * t + 1) * DD + d);
    a.x += w0 * y0.x + w1 * y1.x;
    a.y += w0 * y0.y + w1 * y1.y;
    a.z += w0 * y0.z + w1 * y1.z;
    a.w += w0 * y0.w + w1 * y1.w;
    *reinterpret_cast<float4*>(x + (long)t * DD + d) = a;
}

// ---------------- launch ----------------
extern "C" void kernel_launch(void* const* d_in, const int* in_sizes, int n_in,
                              void* d_out, int out_size)
{
    const int*   token_ids = (const int*)  d_in[0];
    const int*   pos_ids   = (const int*)  d_in[1];
    const float* tok_emb   = (const float*)d_in[2];
    const float* attn_norm = (const float*)d_in[3];
    const float* wq        = (const float*)d_in[4];
    const float* wk        = (const float*)d_in[5];
    const float* wv        = (const float*)d_in[6];
    const float* qn        = (const float*)d_in[7];
    const float* kn        = (const float*)d_in[8];
    const float* wo        = (const float*)d_in[9];
    const float* ffn_norm  = (const float*)d_in[10];
    const float* router_w  = (const float*)d_in[11];
    const float* gate_w    = (const float*)d_in[12];
    const float* up_w      = (const float*)d_in[13];
    const float* down_w    = (const float*)d_in[14];
    const float* fin_norm  = (const float*)d_in[15];

    float *x, *h, *q, *k, *v, *sc, *o, *gt, *up, *y, *rlog, *pw;
    int *cnt, *ptok, *ppair;
    cudaGetSymbolAddress((void**)&x,  g_x);
    cudaGetSymbolAddress((void**)&h,  g_h);
    cudaGetSymbolAddress((void**)&q,  g_q);
    cudaGetSymbolAddress((void**)&k,  g_k);
    cudaGetSymbolAddress((void**)&v,  g_v);
    cudaGetSymbolAddress((void**)&sc, g_scores);
    cudaGetSymbolAddress((void**)&o,  g_o);
    cudaGetSymbolAddress((void**)&gt, g_gate);
    cudaGetSymbolAddress((void**)&up, g_up);
    cudaGetSymbolAddress((void**)&y,  g_y);
    cudaGetSymbolAddress((void**)&rlog, g_rlog);
    cudaGetSymbolAddress((void**)&pw,   g_pairw);
    cudaGetSymbolAddress((void**)&cnt,  g_cnt);
    cudaGetSymbolAddress((void**)&ptok, g_ptok);
    cudaGetSymbolAddress((void**)&ppair,g_ppair);

    embed_kernel<<<TT, 256>>>(token_ids, tok_emb, x);

    for (int l = 0; l < LL; l++) {
        // ---- attention ----
        rmsnorm_kernel<<<TT, 256>>>(x, attn_norm + (long)l * DD, h);
        gemm_kernel<false,false><<<dim3(QD/BN, TT/BM), 256>>>(h, wq + (long)l*DD*QD, q, TT, QD, DD, DD, QD, QD);
        gemm_kernel<false,false><<<dim3(KD/BN, TT/BM), 256>>>(h, wk + (long)l*DD*KD, k, TT, KD, DD, DD, KD, KD);
        gemm_kernel<false,false><<<dim3(KD/BN, TT/BM), 256>>>(h, wv + (long)l*DD*KD, v, TT, KD, DD, DD, KD, KD);
        qk_rope_kernel<<<TT*HH/8, 256>>>(q, qn + (long)l*HDIM, pos_ids, HH, QD);
        qk_rope_kernel<<<TT*KVH/8, 256>>>(k, kn + (long)l*HDIM, pos_ids, KVH, KD);
        attn_scores_kernel<<<dim3(SS/BN, SS/BM, BB*HH), 256>>>(q, k, sc);
        softmax_kernel<<<dim3(SS, BB*HH), 256>>>(sc);
        attn_pv_kernel<<<dim3(1, SS/BM, BB*HH), 256>>>(sc, v, o);
        gemm_kernel<false,true><<<dim3(DD/BN, TT/BM), 256>>>(o, wo + (long)l*QD*DD, x, TT, DD, QD, QD, DD, DD);

        // ---- MoE FFN ----
        rmsnorm_kernel<<<TT, 256>>>(x, ffn_norm + (long)l * DD, h);
        router_kernel<<<TT, 256>>>(h, router_w + (long)l*DD*EE, rlog);
        cudaMemsetAsync(cnt, 0, EE * sizeof(int));
        assign_kernel<<<TT/256, 256>>>(rlog, cnt, ptok, ppair, pw);
        moe_gemm_kernel<<<dim3(FF/BN, 2*TT/BM, EE), 256>>>(
            h, gate_w + (long)l*EE*DD*FF, (long)DD*FF, gt, FF, DD, DD, FF, FF, ptok, ppair, cnt);
        moe_gemm_kernel<<<dim3(FF/BN, 2*TT/BM, EE), 256>>>(
            h, up_w + (long)l*EE*DD*FF, (long)DD*FF, up, FF, DD, DD, FF, FF, ptok, ppair, cnt);
        silu_mul_kernel<<<(2*TT*FF)/256, 256>>>(gt, up);
        moe_gemm_kernel<<<dim3(DD/BN, 2*TT/BM, EE), 256>>>(
            gt, down_w + (long)l*EE*FF*DD, (long)FF*DD, y, DD, FF, FF, DD, DD, ppair, ppair, cnt);
        combine_kernel<<<TT, 256>>>(x, y, pw);
    }

    // ---- final norm + tied lm_head (NT gemm vs tok_emb) ----
    rmsnorm_kernel<<<TT, 256>>>(x, fin_norm, h);
    gemm_kernel<true,false><<<dim3(VV/BN, TT/BM), 256>>>(
        h, tok_emb, (float*)d_out, TT, VV, DD, DD, DD, VV);
}

// round 6
// speedup vs baseline: 2.3159x; 2.3159x over previous
#include <cuda_runtime.h>
#include <cuda_bf16.h>
#include <cstdint>
#include <math.h>

// ---------------- model constants ----------------
#define TT 2048      // B*S tokens
#define BB 2
#define SS 1024
#define DD 1024
#define HH 16
#define KVH 4
#define HDIM 64
#define LL 4
#define EE 8
#define FF 1024
#define VV 32000
#define CAP 4096
#define QD (HH*HDIM)   // 1024
#define KD (KVH*HDIM)  // 256
#define ATT_SCALE 0.125f
#define RMS_EPS 1e-6f

// ---------------- scratch ----------------
__device__ float g_x[TT*DD];
__device__ float g_h[TT*DD];
__device__ float g_q[TT*QD];
__device__ float g_k[TT*KD];
__device__ float g_v[TT*KD];
__device__ float g_scores[(long)BB*HH*SS*SS];
__device__ float g_o[TT*QD];
__device__ float g_gate[2*TT*FF];
__device__ float g_up[2*TT*FF];
__device__ float g_y[2*TT*DD];
__device__ float g_rlog[TT*EE];
__device__ float g_pairw[2*TT];
__device__ int   g_cnt[EE];
__device__ int   g_ptok[EE*CAP];
__device__ int   g_ppair[EE*CAP];

__device__ __forceinline__ float warpReduceSum(float v){
#pragma unroll
    for (int o = 16; o; o >>= 1) v += __shfl_xor_sync(0xffffffffu, v, o);
    return v;
}

__device__ __forceinline__ uint32_t f2tf(float x){
    uint32_t r; asm("cvt.rna.tf32.f32 %0, %1;" : "=r"(r) : "f"(x)); return r;
}
// split fp32 into tf32 hi + tf32 lo  (x ≈ hi + lo, ~21 mantissa bits total)
__device__ __forceinline__ void split_tf(float x, uint32_t& hi, uint32_t& lo){
    uint32_t h = f2tf(x);
    float r = x - __uint_as_float(h);
    hi = h; lo = f2tf(r);
}

// ============== tf32x3 mma GEMM: 128x128 block, BK=16, 8 warps ==============
constexpr int BM = 128, BN = 128, BK = 16;
constexpr int AST = 20;    // padded stride for [row][k] tiles (A, and B when TB)
constexpr int BSTF = 136;  // padded stride for [k][n] B tile (TB=false)
constexpr int TBUF = 2560; // floats per buffer (covers 128*20 and 16*136)

#define MMA8(d, a, b) \
  asm volatile("mma.sync.aligned.m16n8k8.row.col.f32.tf32.tf32.f32 " \
    "{%0,%1,%2,%3},{%4,%5,%6,%7},{%8,%9},{%0,%1,%2,%3};" \
    : "+f"(d[0]),"+f"(d[1]),"+f"(d[2]),"+f"(d[3]) \
    : "r"(a[0]),"r"(a[1]),"r"(a[2]),"r"(a[3]),"r"(b[0]),"r"(b[1]))

template<bool TB, bool ADD, bool GATHER>
__device__ __forceinline__ void mma_body(
    const float* __restrict__ A, const float* __restrict__ B, float* __restrict__ C,
    int M, int N, int K, int lda, int ldb, int ldc,
    int m0, int n0, float alpha,
    const int* __restrict__ aidx, const int* __restrict__ cidx)
{
    __shared__ float sA[2*TBUF];
    __shared__ float sB[2*TBUF];
    const int tid = threadIdx.x;
    const int lane = tid & 31, wid = tid >> 5;
    const int wm = wid & 1, wn = wid >> 1;       // 2 x 4 warps, 64x32 tiles
    const int g = lane >> 2, tq = lane & 3;

    float acc[4][4][4];
#pragma unroll
    for (int mt=0; mt<4; mt++)
#pragma unroll
        for (int nt=0; nt<4; nt++)
#pragma unroll
            for (int i=0;i<4;i++) acc[mt][nt][i]=0.f;

    // ---- global->smem mappings (fixed per thread) ----
    const float* aptr[2]; int aoff[2];
#pragma unroll
    for (int i=0;i<2;i++){
        int idx = tid + i*256;
        int row = idx>>2, seg=(idx&3)*4;
        int m = m0 + row;
        bool ok = m < M;
        int r = ok ? (GATHER ? aidx[m] : m) : 0;
        aptr[i] = ok ? (A + (long)r*lda + seg) : nullptr;
        aoff[i] = row*AST + seg;
    }
    const float* bptr[2]; int boff[2];
#pragma unroll
    for (int i=0;i<2;i++){
        int idx = tid + i*256;
        if (!TB){
            int k = idx>>5, nseg=(idx&31)*4;
            bool ok = (n0+nseg) < N;
            bptr[i] = ok ? (B + (long)k*ldb + n0 + nseg) : nullptr;
            boff[i] = k*BSTF + nseg;
        } else {
            int n = idx>>2, kseg=(idx&3)*4;
            bool ok = (n0+n) < N;
            bptr[i] = ok ? (B + (long)(n0+n)*ldb + kseg) : nullptr;
            boff[i] = n*AST + kseg;
        }
    }

    const float4 Z4 = make_float4(0.f,0.f,0.f,0.f);
    // ---- prologue: fill buffer 0 (raw fp32) ----
#pragma unroll
    for (int i=0;i<2;i++)
        *reinterpret_cast<float4*>(sA + aoff[i]) =
            aptr[i] ? *reinterpret_cast<const float4*>(aptr[i]) : Z4;
#pragma unroll
    for (int i=0;i<2;i++)
        *reinterpret_cast<float4*>(sB + boff[i]) =
            bptr[i] ? *reinterpret_cast<const float4*>(bptr[i]) : Z4;
    __syncthreads();

    const int nk = K / BK;
    for (int kb = 0; kb < nk; kb++){
        const int cur = kb & 1;
        float4 pa[2], pb[2];
        if (kb+1 < nk){
#pragma unroll
            for (int i=0;i<2;i++)
                pa[i] = aptr[i] ? *reinterpret_cast<const float4*>(aptr[i] + (kb+1)*BK) : Z4;
#pragma unroll
            for (int i=0;i<2;i++){
                long adv = TB ? (long)(kb+1)*BK : (long)(kb+1)*BK*ldb;
                pb[i] = bptr[i] ? *reinterpret_cast<const float4*>(bptr[i] + adv) : Z4;
            }
        }
        const float* pA = sA + cur*TBUF;
        const float* pB = sB + cur*TBUF;
#pragma unroll
        for (int ks=0; ks<2; ks++){
            const int kk = ks*8;
            uint32_t ah[4][4], al[4][4];
#pragma unroll
            for (int mt=0; mt<4; mt++){
                const float* ap = pA + (wm*64 + mt*16 + g)*AST + kk + tq;
                split_tf(ap[0],        ah[mt][0], al[mt][0]);
                split_tf(ap[8*AST],    ah[mt][1], al[mt][1]);
                split_tf(ap[4],        ah[mt][2], al[mt][2]);
                split_tf(ap[8*AST+4],  ah[mt][3], al[mt][3]);
            }
#pragma unroll
            for (int nt=0; nt<4; nt++){
                float b0, b1;
                if (!TB){
                    const float* bp = pB + (kk+tq)*BSTF + wn*32 + nt*8 + g;
                    b0 = bp[0]; b1 = bp[4*BSTF];
                } else {
                    const float* bp = pB + (wn*32 + nt*8 + g)*AST + kk + tq;
                    b0 = bp[0]; b1 = bp[4];
                }
                uint32_t bh[2], bl[2];
                split_tf(b0, bh[0], bl[0]);
                split_tf(b1, bh[1], bl[1]);
#pragma unroll
                for (int mt=0; mt<4; mt++){
                    MMA8(acc[mt][nt], al[mt], bh);   // lo*hi correction
                    MMA8(acc[mt][nt], ah[mt], bl);   // hi*lo correction
                    MMA8(acc[mt][nt], ah[mt], bh);   // main product
                }
            }
        }
        if (kb+1 < nk){
            float* dA = sA + (1-cur)*TBUF;
            float* dB = sB + (1-cur)*TBUF;
#pragma unroll
            for (int i=0;i<2;i++) *reinterpret_cast<float4*>(dA + aoff[i]) = pa[i];
#pragma unroll
            for (int i=0;i<2;i++) *reinterpret_cast<float4*>(dB + boff[i]) = pb[i];
            __syncthreads();
        }
    }

    // ---- epilogue ----
#pragma unroll
    for (int mt=0; mt<4; mt++){
        int r0 = m0 + wm*64 + mt*16 + g;
        int r1 = r0 + 8;
#pragma unroll
        for (int rr=0; rr<2; rr++){
            int m = rr ? r1 : r0;
            if (m >= M) continue;
            long crow = GATHER ? (long)cidx[m] : (long)m;
            float* cp = C + crow*ldc;
#pragma unroll
            for (int nt=0; nt<4; nt++){
                int c0 = n0 + wn*32 + nt*8 + tq*2;
                if (c0 >= N) continue;
                float v0 = acc[mt][nt][rr*2+0]*alpha;
                float v1 = acc[mt][nt][rr*2+1]*alpha;
                if (ADD){ cp[c0] += v0; cp[c0+1] += v1; }
                else { *reinterpret_cast<float2*>(cp + c0) = make_float2(v0, v1); }
            }
        }
    }
}

template<bool TB, bool ADD>
__global__ void __launch_bounds__(256)
mma_gemm(const float* __restrict__ A, const float* __restrict__ B, float* __restrict__ C,
         int M, int N, int K, int lda, int ldb, int ldc)
{
    mma_body<TB,ADD,false>(A,B,C,M,N,K,lda,ldb,ldc,
                           blockIdx.y*BM, blockIdx.x*BN, 1.f, nullptr, nullptr);
}

__global__ void __launch_bounds__(256)
moe_mma_gemm(const float* __restrict__ A, const float* __restrict__ Bbase, long bstride,
             float* __restrict__ C, int N, int K, int lda, int ldb, int ldc,
             const int* __restrict__ aidx, const int* __restrict__ cidx,
             const int* __restrict__ cnt)
{
    int e = blockIdx.z;
    int M = cnt[e];
    int m0 = blockIdx.y * BM;
    if (m0 >= M) return;
    mma_body<false,false,true>(A, Bbase + (long)e*bstride, C, M, N, K, lda, ldb, ldc,
                               m0, blockIdx.x*BN, 1.f, aidx + e*CAP, cidx + e*CAP);
}

__global__ void __launch_bounds__(256)
attn_scores_mma(const float* __restrict__ q, const float* __restrict__ k,
                float* __restrict__ scores)
{
    int z = blockIdx.z;
    int b = z / HH, h = z % HH;
    int m0 = blockIdx.y * BM, n0 = blockIdx.x * BN;
    if (n0 >= m0 + BM) return;   // fully masked causal tile
    const float* A = q + (long)b*SS*QD + h*HDIM;
    const float* B = k + (long)b*SS*KD + (h>>2)*HDIM;
    float* C = scores + (long)z*SS*SS;
    mma_body<true,false,false>(A,B,C, SS,SS,HDIM, QD,KD,SS, m0,n0, ATT_SCALE, nullptr,nullptr);
}

__global__ void __launch_bounds__(256)
attn_pv_mma(const float* __restrict__ scores, const float* __restrict__ v,
            float* __restrict__ o)
{
    int z = blockIdx.z;
    int b = z / HH, h = z % HH;
    const float* A = scores + (long)z*SS*SS;
    const float* B = v + (long)b*SS*KD + (h>>2)*HDIM;
    float* C = o + (long)b*SS*QD + h*HDIM;
    mma_body<false,false,false>(A,B,C, SS,HDIM,SS, SS,KD,QD, blockIdx.y*BM, 0, 1.f, nullptr,nullptr);
}

// ---------------- elementwise / small kernels ----------------
__global__ void embed_kernel(const int* __restrict__ ids, const float* __restrict__ emb,
                             float* __restrict__ x)
{
    int t = blockIdx.x;
    long src = (long)ids[t] * DD;
    int d = threadIdx.x * 4;
    *reinterpret_cast<float4*>(x + (long)t*DD + d) =
        *reinterpret_cast<const float4*>(emb + src + d);
}

__global__ void rmsnorm_kernel(const float* __restrict__ in, const float* __restrict__ w,
                               float* __restrict__ out)
{
    int t = blockIdx.x;
    const float* row = in + (long)t * DD;
    int d = threadIdx.x * 4;
    float4 va = *reinterpret_cast<const float4*>(row + d);
    float ss = va.x*va.x + va.y*va.y + va.z*va.z + va.w*va.w;
    __shared__ float red[8];
    __shared__ float bc;
    ss = warpReduceSum(ss);
    if ((threadIdx.x & 31) == 0) red[threadIdx.x >> 5] = ss;
    __syncthreads();
    if (threadIdx.x == 0) {
        float s = 0.f;
#pragma unroll
        for (int i = 0; i < 8; i++) s += red[i];
        bc = rsqrtf(s / (float)DD + RMS_EPS);
    }
    __syncthreads();
    float r = bc;
    float4 wv = *reinterpret_cast<const float4*>(w + d);
    float4 ov;
    ov.x = va.x*r*wv.x; ov.y = va.y*r*wv.y;
    ov.z = va.z*r*wv.z; ov.w = va.w*r*wv.w;
    *reinterpret_cast<float4*>(out + (long)t*DD + d) = ov;
}

__global__ void qk_rope_kernel(float* __restrict__ buf, const float* __restrict__ nw,
                               const int* __restrict__ pos_ids, int nheads, int rowstride)
{
    int gw = (blockIdx.x * blockDim.x + threadIdx.x) >> 5;
    int lane = threadIdx.x & 31;
    int t = gw / nheads;
    int hh = gw - t * nheads;
    if (t >= TT) return;
    float* p = buf + (long)t * rowstride + hh * HDIM;
    float v0 = p[lane], v1 = p[lane + 32];
    float ss = warpReduceSum(v0*v0 + v1*v1);
    float r = rsqrtf(ss / 64.f + RMS_EPS);
    v0 *= r * nw[lane];
    v1 *= r * nw[lane + 32];
    float inv_freq = (float)pow(1000000.0, -(double)lane / 32.0);
    float ang = (float)pos_ids[t] * inv_freq;
    float c, s;
    sincosf(ang, &s, &c);
    p[lane]      = v0 * c - v1 * s;
    p[lane + 32] = v1 * c + v0 * s;
}

__global__ void softmax_kernel(float* __restrict__ scores)
{
    long z = blockIdx.y;
    int i = blockIdx.x;
    float* row = scores + (z * SS + i) * (long)SS;
    int valid = i + 1;
    __shared__ float red[8];
    __shared__ float bc;
    float m = -1e30f;
    for (int j = threadIdx.x; j < valid; j += 256) m = fmaxf(m, row[j]);
#pragma unroll
    for (int o = 16; o; o >>= 1) m = fmaxf(m, __shfl_xor_sync(0xffffffffu, m, o));
    if ((threadIdx.x & 31) == 0) red[threadIdx.x >> 5] = m;
    __syncthreads();
    if (threadIdx.x == 0) {
        float mm = -1e30f;
#pragma unroll
        for (int i2 = 0; i2 < 8; i2++) mm = fmaxf(mm, red[i2]);
        bc = mm;
    }
    __syncthreads();
    m = bc;
    float s = 0.f;
    for (int j = threadIdx.x; j < valid; j += 256) s += expf(row[j] - m);
    s = warpReduceSum(s);
    if ((threadIdx.x & 31) == 0) red[threadIdx.x >> 5] = s;
    __syncthreads();
    if (threadIdx.x == 0) {
        float t = 0.f;
#pragma unroll
        for (int i2 = 0; i2 < 8; i2++) t += red[i2];
        bc = t;
    }
    __syncthreads();
    float inv = 1.f / bc;
    for (int j = threadIdx.x; j < valid; j += 256) row[j] = expf(row[j] - m) * inv;
    for (int j = valid + threadIdx.x; j < SS; j += 256) row[j] = 0.f;
}

__global__ void router_kernel(const float* __restrict__ h, const float* __restrict__ rw,
                              float* __restrict__ lg)
{
    int t = blockIdx.x;
    __shared__ float sh[DD];
    for (int d = threadIdx.x; d < DD; d += 256) sh[d] = h[(long)t * DD + d];
    __syncthreads();
    int w = threadIdx.x >> 5, lane = threadIdx.x & 31;
    float s = 0.f;
    for (int d = lane; d < DD; d += 32) s += sh[d] * rw[d * EE + w];
    s = warpReduceSum(s);
    if (lane == 0) lg[t * EE + w] = s;
}

__global__ void assign_kernel(const float* __restrict__ lg, int* __restrict__ cnt,
                              int* __restrict__ ptok, int* __restrict__ ppair,
                              float* __restrict__ pw)
{
    int t = blockIdx.x * blockDim.x + threadIdx.x;
    if (t >= TT) return;
    float l1 = -1e30f, l2 = -1e30f;
    int i1 = 0, i2 = 0;
#pragma unroll
    for (int e = 0; e < EE; e++) {
        float v = lg[t * EE + e];
        if (v > l1) { l2 = l1; i2 = i1; l1 = v; i1 = e; }
        else if (v > l2) { l2 = v; i2 = e; }
    }
    float e2 = expf(l2 - l1);
    float w1 = 1.f / (1.f + e2);
    float w2 = e2 / (1.f + e2);
    int p = atomicAdd(&cnt[i1], 1);
    ptok[i1 * CAP + p] = t;  ppair[i1 * CAP + p] = 2 * t;
    p = atomicAdd(&cnt[i2], 1);
    ptok[i2 * CAP + p] = t;  ppair[i2 * CAP + p] = 2 * t + 1;
    pw[2 * t] = w1;  pw[2 * t + 1] = w2;
}

__global__ void silu_mul_kernel(float* __restrict__ g, const float* __restrict__ u)
{
    long i = (long)blockIdx.x * blockDim.x + threadIdx.x;
    float gv = g[i];
    float sg = gv / (1.f + expf(-gv));
    g[i] = sg * u[i];
}

__global__ void combine_kernel(float* __restrict__ x, const float* __restrict__ y,
                               const float* __restrict__ pw)
{
    int t = blockIdx.x;
    float w0 = pw[2 * t], w1 = pw[2 * t + 1];
    int d = threadIdx.x * 4;
    float4 a  = *reinterpret_cast<float4*>(x + (long)t*DD + d);
    float4 y0 = *reinterpret_cast<const float4*>(y + (long)(2*t)*DD + d);
    float4 y1 = *reinterpret_cast<const float4*>(y + (long)(2*t+1)*DD + d);
    a.x += w0*y0.x + w1*y1.x;
    a.y += w0*y0.y + w1*y1.y;
    a.z += w0*y0.z + w1*y1.z;
    a.w += w0*y0.w + w1*y1.w;
    *reinterpret_cast<float4*>(x + (long)t*DD + d) = a;
}

// ---------------- launch ----------------
extern "C" void kernel_launch(void* const* d_in, const int* in_sizes, int n_in,
                              void* d_out, int out_size)
{
    const int*   token_ids = (const int*)  d_in[0];
    const int*   pos_ids   = (const int*)  d_in[1];
    const float* tok_emb   = (const float*)d_in[2];
    const float* attn_norm = (const float*)d_in[3];
    const float* wq        = (const float*)d_in[4];
    const float* wk        = (const float*)d_in[5];
    const float* wv        = (const float*)d_in[6];
    const float* qn        = (const float*)d_in[7];
    const float* kn        = (const float*)d_in[8];
    const float* wo        = (const float*)d_in[9];
    const float* ffn_norm  = (const float*)d_in[10];
    const float* router_w  = (const float*)d_in[11];
    const float* gate_w    = (const float*)d_in[12];
    const float* up_w      = (const float*)d_in[13];
    const float* down_w    = (const float*)d_in[14];
    const float* fin_norm  = (const float*)d_in[15];

    float *x, *h, *q, *k, *v, *sc, *o, *gt, *up, *y, *rlog, *pw;
    int *cnt, *ptok, *ppair;
    cudaGetSymbolAddress((void**)&x,  g_x);
    cudaGetSymbolAddress((void**)&h,  g_h);
    cudaGetSymbolAddress((void**)&q,  g_q);
    cudaGetSymbolAddress((void**)&k,  g_k);
    cudaGetSymbolAddress((void**)&v,  g_v);
    cudaGetSymbolAddress((void**)&sc, g_scores);
    cudaGetSymbolAddress((void**)&o,  g_o);
    cudaGetSymbolAddress((void**)&gt, g_gate);
    cudaGetSymbolAddress((void**)&up, g_up);
    cudaGetSymbolAddress((void**)&y,  g_y);
    cudaGetSymbolAddress((void**)&rlog, g_rlog);
    cudaGetSymbolAddress((void**)&pw,   g_pairw);
    cudaGetSymbolAddress((void**)&cnt,  g_cnt);
    cudaGetSymbolAddress((void**)&ptok, g_ptok);
    cudaGetSymbolAddress((void**)&ppair,g_ppair);

    embed_kernel<<<TT, 256>>>(token_ids, tok_emb, x);

    for (int l = 0; l < LL; l++) {
        // ---- attention ----
        rmsnorm_kernel<<<TT, 256>>>(x, attn_norm + (long)l*DD, h);
        mma_gemm<false,false><<<dim3(QD/BN, TT/BM), 256>>>(h, wq + (long)l*DD*QD, q, TT, QD, DD, DD, QD, QD);
        mma_gemm<false,false><<<dim3(KD/BN, TT/BM), 256>>>(h, wk + (long)l*DD*KD, k, TT, KD, DD, DD, KD, KD);
        mma_gemm<false,false><<<dim3(KD/BN, TT/BM), 256>>>(h, wv + (long)l*DD*KD, v, TT, KD, DD, DD, KD, KD);
        qk_rope_kernel<<<TT*HH/8, 256>>>(q, qn + (long)l*HDIM, pos_ids, HH, QD);
        qk_rope_kernel<<<TT*KVH/8, 256>>>(k, kn + (long)l*HDIM, pos_ids, KVH, KD);
        attn_scores_mma<<<dim3(SS/BN, SS/BM, BB*HH), 256>>>(q, k, sc);
        softmax_kernel<<<dim3(SS, BB*HH), 256>>>(sc);
        attn_pv_mma<<<dim3(1, SS/BM, BB*HH), 256>>>(sc, v, o);
        mma_gemm<false,true><<<dim3(DD/BN, TT/BM), 256>>>(o, wo + (long)l*QD*DD, x, TT, DD, QD, QD, DD, DD);

        // ---- MoE FFN ----
        rmsnorm_kernel<<<TT, 256>>>(x, ffn_norm + (long)l*DD, h);
        router_kernel<<<TT, 256>>>(h, router_w + (long)l*DD*EE, rlog);
        cudaMemsetAsync(cnt, 0, EE * sizeof(int));
        assign_kernel<<<TT/256, 256>>>(rlog, cnt, ptok, ppair, pw);
        moe_mma_gemm<<<dim3(FF/BN, 2*TT/BM, EE), 256>>>(
            h, gate_w + (long)l*EE*DD*FF, (long)DD*FF, gt, FF, DD, DD, FF, FF, ptok, ppair, cnt);
        moe_mma_gemm<<<dim3(FF/BN, 2*TT/BM, EE), 256>>>(
            h, up_w + (long)l*EE*DD*FF, (long)DD*FF, up, FF, DD, DD, FF, FF, ptok, ppair, cnt);
        silu_mul_kernel<<<(2*TT*FF)/256, 256>>>(gt, up);
        moe_mma_gemm<<<dim3(DD/BN, 2*TT/BM, EE), 256>>>(
            gt, down_w + (long)l*EE*FF*DD, (long)FF*DD, y, DD, FF, FF, DD, DD, ppair, ppair, cnt);
        combine_kernel<<<TT, 256>>>(x, y, pw);
    }

    // ---- final norm + tied lm_head ----
    rmsnorm_kernel<<<TT, 256>>>(x, fin_norm, h);
    mma_gemm<true,false><<<dim3(VV/BN, TT/BM), 256>>>(
        h, tok_emb, (float*)d_out, TT, VV, DD, DD, DD, VV);
}

// round 10
// speedup vs baseline: 3.2983x; 1.4242x over previous
#include <cuda_runtime.h>
#include <cuda_bf16.h>
#include <cstdint>
#include <math.h>

// ---------------- model constants ----------------
#define TT 2048      // B*S tokens
#define BB 2
#define SS 1024
#define DD 1024
#define HH 16
#define KVH 4
#define HDIM 64
#define LL 4
#define EE 8
#define FF 1024
#define VV 32000
#define CAP 4096
#define QD (HH*HDIM)   // 1024
#define KD (KVH*HDIM)  // 256
#define ATT_SCALE 0.125f
#define RMS_EPS 1e-6f

// ---------------- scratch ----------------
__device__ float g_x[TT*DD];
__device__ float g_h[TT*DD];
__device__ float g_q[TT*QD];
__device__ float g_k[TT*KD];
__device__ float g_v[TT*KD];
__device__ float g_scores[(long)BB*HH*SS*SS];
__device__ float g_o[TT*QD];
__device__ float g_gate[2*TT*FF];
__device__ float g_up[2*TT*FF];
__device__ float g_y[2*TT*DD];
__device__ float g_rlog[TT*EE];
__device__ float g_pairw[2*TT];
__device__ int   g_cnt[EE];
__device__ int   g_ptok[EE*CAP];
__device__ int   g_ppair[EE*CAP];

__device__ __forceinline__ float warpReduceSum(float v){
#pragma unroll
    for (int o = 16; o; o >>= 1) v += __shfl_xor_sync(0xffffffffu, v, o);
    return v;
}

// split two fp32 into packed bf16 hi-pair and lo-pair (low half = first elem)
__device__ __forceinline__ void split_pack(float x0, float x1, uint32_t& h, uint32_t& l){
    __nv_bfloat16 h0 = __float2bfloat16(x0);
    __nv_bfloat16 h1 = __float2bfloat16(x1);
    __nv_bfloat16 l0 = __float2bfloat16(x0 - __bfloat162float(h0));
    __nv_bfloat16 l1 = __float2bfloat16(x1 - __bfloat162float(h1));
    __nv_bfloat162 hh = __halves2bfloat162(h0, h1);
    __nv_bfloat162 ll = __halves2bfloat162(l0, l1);
    h = *reinterpret_cast<uint32_t*>(&hh);
    l = *reinterpret_cast<uint32_t*>(&ll);
}

// ============== bf16x2 (3-product) mma GEMM: 128x128 block, BK=16, 8 warps ==============
constexpr int BM = 128, BN = 128, BK = 16;
constexpr int SAK  = 12;   // u32 stride for [row][kpair] planes (8 pairs + pad, conflict-free)
constexpr int BNST = 136;  // u32 stride for [kpair][n] planes (non-TB B)
constexpr int PLSZ = 1536; // u32 per plane (covers 128*12 and 8*136)

#define MMAB(d, a, b) \
  asm volatile("mma.sync.aligned.m16n8k16.row.col.f32.bf16.bf16.f32 " \
    "{%0,%1,%2,%3},{%4,%5,%6,%7},{%8,%9},{%0,%1,%2,%3};" \
    : "+f"(d[0]),"+f"(d[1]),"+f"(d[2]),"+f"(d[3]) \
    : "r"(a[0]),"r"(a[1]),"r"(a[2]),"r"(a[3]),"r"(b[0]),"r"(b[1]))

template<bool TB, bool ADD, bool GATHER>
__device__ __forceinline__ void mma_body(
    const float* __restrict__ A, const float* __restrict__ B, float* __restrict__ C,
    int M, int N, int K, int lda, int ldb, int ldc,
    int m0, int n0, float alpha,
    const int* __restrict__ aidx, const int* __restrict__ cidx)
{
    // layout: [buf][plane(hi=0,lo=1)][PLSZ]
    __shared__ uint32_t sA[2][2][PLSZ];
    __shared__ uint32_t sB[2][2][PLSZ];
    const int tid = threadIdx.x;
    const int lane = tid & 31, wid = tid >> 5;
    const int wm = wid & 1, wn = wid >> 1;       // 2 x 4 warps, 64x32 tiles
    const int g = lane >> 2, tq = lane & 3;

    float acc[4][4][4];
#pragma unroll
    for (int mt=0; mt<4; mt++)
#pragma unroll
        for (int nt=0; nt<4; nt++)
#pragma unroll
            for (int i=0;i<4;i++) acc[mt][nt][i]=0.f;

    // ---- global->smem mappings (fixed per thread) ----
    // A tile: 128 rows x 16 k = 2048 floats; 512 float4 loads (2 per thread)
    const float* aptr[2]; int aoff[2];   // aoff in u32 units into plane
#pragma unroll
    for (int i=0;i<2;i++){
        int idx = tid + i*256;
        int row = idx>>2, seg=(idx&3)*4;     // seg: k offset (0,4,8,12)
        int m = m0 + row;
        bool ok = m < M;
        int r = ok ? (GATHER ? aidx[m] : m) : 0;
        aptr[i] = ok ? (A + (long)r*lda + seg) : nullptr;
        aoff[i] = row*SAK + seg/2;
    }
    // B tile:
    //  !TB: 16 k-rows x 128 n. Each thread covers rows {2kp, 2kp+1} x 4 n -> 8 floats.
    //       256 threads * 8 = 2048 floats. ONE load slot per thread.
    //  TB:  128 n-rows x 16 k; same shape as A -> 2 slots per thread.
    const float* bptrN = nullptr; int boffN = 0;
    const float* bptrT[2] = {nullptr,nullptr}; int boffT[2] = {0,0};
    if (!TB){
        int kp = tid >> 5;              // 0..7
        int nseg = (tid & 31) * 4;      // 0..124
        bool ok = (n0 + nseg) < N;
        bptrN = ok ? (B + (long)(2*kp)*ldb + n0 + nseg) : nullptr;
        boffN = kp*BNST + nseg;
    } else {
#pragma unroll
        for (int i=0;i<2;i++){
            int idx = tid + i*256;
            int n = idx>>2, kseg=(idx&3)*4;
            bool ok = (n0+n) < N;
            bptrT[i] = ok ? (B + (long)(n0+n)*ldb + kseg) : nullptr;
            boffT[i] = n*SAK + kseg/2;
        }
    }

    const float4 Z4 = make_float4(0.f,0.f,0.f,0.f);

    // ---- prologue: fill buffer 0 ----
    {
#pragma unroll
        for (int i=0;i<2;i++){
            float4 v = aptr[i] ? *reinterpret_cast<const float4*>(aptr[i]) : Z4;
            uint32_t h0,l0,h1,l1;
            split_pack(v.x, v.y, h0, l0);
            split_pack(v.z, v.w, h1, l1);
            *reinterpret_cast<uint2*>(&sA[0][0][aoff[i]]) = make_uint2(h0,h1);
            *reinterpret_cast<uint2*>(&sA[0][1][aoff[i]]) = make_uint2(l0,l1);
        }
        if (!TB){
            float4 v0 = bptrN ? *reinterpret_cast<const float4*>(bptrN) : Z4;
            float4 v1 = bptrN ? *reinterpret_cast<const float4*>(bptrN + ldb) : Z4;
            uint32_t h0,l0,h1,l1,h2,l2,h3,l3;
            split_pack(v0.x, v1.x, h0, l0);
            split_pack(v0.y, v1.y, h1, l1);
            split_pack(v0.z, v1.z, h2, l2);
            split_pack(v0.w, v1.w, h3, l3);
            *reinterpret_cast<uint4*>(&sB[0][0][boffN]) = make_uint4(h0,h1,h2,h3);
            *reinterpret_cast<uint4*>(&sB[0][1][boffN]) = make_uint4(l0,l1,l2,l3);
        } else {
#pragma unroll
            for (int i=0;i<2;i++){
                float4 v = bptrT[i] ? *reinterpret_cast<const float4*>(bptrT[i]) : Z4;
                uint32_t h0,l0,h1,l1;
                split_pack(v.x, v.y, h0, l0);
                split_pack(v.z, v.w, h1, l1);
                *reinterpret_cast<uint2*>(&sB[0][0][boffT[i]]) = make_uint2(h0,h1);
                *reinterpret_cast<uint2*>(&sB[0][1][boffT[i]]) = make_uint2(l0,l1);
            }
        }
    }
    __syncthreads();

    const int nk = K / BK;
    for (int kb = 0; kb < nk; kb++){
        const int cur = kb & 1;
        float4 pa[2], pb0, pb1, pbt[2];
        if (kb+1 < nk){
#pragma unroll
            for (int i=0;i<2;i++)
                pa[i] = aptr[i] ? *reinterpret_cast<const float4*>(aptr[i] + (kb+1)*BK) : Z4;
            if (!TB){
                long adv = (long)(kb+1)*BK*ldb;
                pb0 = bptrN ? *reinterpret_cast<const float4*>(bptrN + adv) : Z4;
                pb1 = bptrN ? *reinterpret_cast<const float4*>(bptrN + adv + ldb) : Z4;
            } else {
#pragma unroll
                for (int i=0;i<2;i++)
                    pbt[i] = bptrT[i] ? *reinterpret_cast<const float4*>(bptrT[i] + (kb+1)*BK) : Z4;
            }
        }

        const uint32_t* Ah = sA[cur][0];
        const uint32_t* Al = sA[cur][1];
        const uint32_t* Bh = sB[cur][0];
        const uint32_t* Bl = sB[cur][1];

        uint32_t ah[4][4], al[4][4], bh[4][2], bl[4][2];
#pragma unroll
        for (int mt=0; mt<4; mt++){
            int r = wm*64 + mt*16 + g;
            int o0 = r*SAK + tq, o1 = (r+8)*SAK + tq;
            ah[mt][0]=Ah[o0];   ah[mt][1]=Ah[o1];
            ah[mt][2]=Ah[o0+4]; ah[mt][3]=Ah[o1+4];
            al[mt][0]=Al[o0];   al[mt][1]=Al[o1];
            al[mt][2]=Al[o0+4]; al[mt][3]=Al[o1+4];
        }
#pragma unroll
        for (int nt=0; nt<4; nt++){
            if (!TB){
                int n = wn*32 + nt*8 + g;
                int o0 = tq*BNST + n;
                int o1 = (tq+4)*BNST + n;
                bh[nt][0]=Bh[o0]; bh[nt][1]=Bh[o1];
                bl[nt][0]=Bl[o0]; bl[nt][1]=Bl[o1];
            } else {
                int n = wn*32 + nt*8 + g;
                int o0 = n*SAK + tq, o1 = n*SAK + tq + 4;
                bh[nt][0]=Bh[o0]; bh[nt][1]=Bh[o1];
                bl[nt][0]=Bl[o0]; bl[nt][1]=Bl[o1];
            }
        }
#pragma unroll
        for (int mt=0; mt<4; mt++)
#pragma unroll
            for (int nt=0; nt<4; nt++){
                MMAB(acc[mt][nt], al[mt], bh[nt]);   // lo*hi
                MMAB(acc[mt][nt], ah[mt], bl[nt]);   // hi*lo
                MMAB(acc[mt][nt], ah[mt], bh[nt]);   // hi*hi
            }

        if (kb+1 < nk){
            const int nxt = 1-cur;
#pragma unroll
            for (int i=0;i<2;i++){
                float4 v = pa[i];
                uint32_t h0,l0,h1,l1;
                split_pack(v.x, v.y, h0, l0);
                split_pack(v.z, v.w, h1, l1);
                *reinterpret_cast<uint2*>(&sA[nxt][0][aoff[i]]) = make_uint2(h0,h1);
                *reinterpret_cast<uint2*>(&sA[nxt][1][aoff[i]]) = make_uint2(l0,l1);
            }
            if (!TB){
                uint32_t h0,l0,h1,l1,h2,l2,h3,l3;
                split_pack(pb0.x, pb1.x, h0, l0);
                split_pack(pb0.y, pb1.y, h1, l1);
                split_pack(pb0.z, pb1.z, h2, l2);
                split_pack(pb0.w, pb1.w, h3, l3);
                *reinterpret_cast<uint4*>(&sB[nxt][0][boffN]) = make_uint4(h0,h1,h2,h3);
                *reinterpret_cast<uint4*>(&sB[nxt][1][boffN]) = make_uint4(l0,l1,l2,l3);
            } else {
#pragma unroll
                for (int i=0;i<2;i++){
                    float4 v = pbt[i];
                    uint32_t h0,l0,h1,l1;
                    split_pack(v.x, v.y, h0, l0);
                    split_pack(v.z, v.w, h1, l1);
                    *reinterpret_cast<uint2*>(&sB[nxt][0][boffT[i]]) = make_uint2(h0,h1);
                    *reinterpret_cast<uint2*>(&sB[nxt][1][boffT[i]]) = make_uint2(l0,l1);
                }
            }
            __syncthreads();
        }
    }

    // ---- epilogue ----
#pragma unroll
    for (int mt=0; mt<4; mt++){
        int r0 = m0 + wm*64 + mt*16 + g;
        int r1 = r0 + 8;
#pragma unroll
        for (int rr=0; rr<2; rr++){
            int m = rr ? r1 : r0;
            if (m >= M) continue;
            long crow = GATHER ? (long)cidx[m] : (long)m;
            float* cp = C + crow*ldc;
#pragma unroll
            for (int nt=0; nt<4; nt++){
                int c0 = n0 + wn*32 + nt*8 + tq*2;
                if (c0 >= N) continue;
                float v0 = acc[mt][nt][rr*2+0]*alpha;
                float v1 = acc[mt][nt][rr*2+1]*alpha;
                if (ADD){ cp[c0] += v0; cp[c0+1] += v1; }
                else { *reinterpret_cast<float2*>(cp + c0) = make_float2(v0, v1); }
            }
        }
    }
}

template<bool TB, bool ADD>
__global__ void __launch_bounds__(256)
mma_gemm(const float* __restrict__ A, const float* __restrict__ B, float* __restrict__ C,
         int M, int N, int K, int lda, int ldb, int ldc)
{
    mma_body<TB,ADD,false>(A,B,C,M,N,K,lda,ldb,ldc,
                           blockIdx.y*BM, blockIdx.x*BN, 1.f, nullptr, nullptr);
}

// fused QKV: grid (12, TT/BM). x: 0-7 -> Q tiles, 8-9 -> K, 10-11 -> V
__global__ void __launch_bounds__(256)
qkv_gemm(const float* __restrict__ h,
         const float* __restrict__ wq, const float* __restrict__ wk, const float* __restrict__ wv,
         float* __restrict__ q, float* __restrict__ k, float* __restrict__ v)
{
    int bx = blockIdx.x;
    const float* B; float* C; int ldx, N, n0;
    if (bx < 8)       { B = wq; C = q; ldx = QD; N = QD; n0 = bx*128; }
    else if (bx < 10) { B = wk; C = k; ldx = KD; N = KD; n0 = (bx-8)*128; }
    else              { B = wv; C = v; ldx = KD; N = KD; n0 = (bx-10)*128; }
    mma_body<false,false,false>(h, B, C, TT, N, DD, DD, ldx, ldx,
                                blockIdx.y*BM, n0, 1.f, nullptr, nullptr);
}

__global__ void __launch_bounds__(256)
moe_mma_gemm(const float* __restrict__ A, const float* __restrict__ Bbase, long bstride,
             float* __restrict__ C, int N, int K, int lda, int ldb, int ldc,
             const int* __restrict__ aidx, const int* __restrict__ cidx,
             const int* __restrict__ cnt)
{
    int e = blockIdx.z;
    int M = cnt[e];
    int m0 = blockIdx.y * BM;
    if (m0 >= M) return;
    mma_body<false,false,true>(A, Bbase + (long)e*bstride, C, M, N, K, lda, ldb, ldc,
                               m0, blockIdx.x*BN, 1.f, aidx + e*CAP, cidx + e*CAP);
}

__global__ void __launch_bounds__(256)
attn_scores_mma(const float* __restrict__ q, const float* __restrict__ k,
                float* __restrict__ scores)
{
    int z = blockIdx.z;
    int b = z / HH, h = z % HH;
    int m0 = blockIdx.y * BM, n0 = blockIdx.x * BN;
    if (n0 >= m0 + BM) return;   // fully masked causal tile
    const float* A = q + (long)b*SS*QD + h*HDIM;
    const float* B = k + (long)b*SS*KD + (h>>2)*HDIM;
    float* C = scores + (long)z*SS*SS;
    mma_body<true,false,false>(A,B,C, SS,SS,HDIM, QD,KD,SS, m0,n0, ATT_SCALE, nullptr,nullptr);
}

__global__ void __launch_bounds__(256)
attn_pv_mma(const float* __restrict__ scores, const float* __restrict__ v,
            float* __restrict__ o)
{
    int z = blockIdx.z;
    int b = z / HH, h = z % HH;
    const float* A = scores + (long)z*SS*SS;
    const float* B = v + (long)b*SS*KD + (h>>2)*HDIM;
    float* C = o + (long)b*SS*QD + h*HDIM;
    mma_body<false,false,false>(A,B,C, SS,HDIM,SS, SS,KD,QD, blockIdx.y*BM, 0, 1.f, nullptr,nullptr);
}

// ---------------- elementwise / small kernels ----------------
__global__ void embed_kernel(const int* __restrict__ ids, const float* __restrict__ emb,
                             float* __restrict__ x)
{
    int t = blockIdx.x;
    long src = (long)ids[t] * DD;
    int d = threadIdx.x * 4;
    *reinterpret_cast<float4*>(x + (long)t*DD + d) =
        *reinterpret_cast<const float4*>(emb + src + d);
}

__global__ void rmsnorm_kernel(const float* __restrict__ in, const float* __restrict__ w,
                               float* __restrict__ out)
{
    int t = blockIdx.x;
    const float* row = in + (long)t * DD;
    int d = threadIdx.x * 4;
    float4 va = *reinterpret_cast<const float4*>(row + d);
    float ss = va.x*va.x + va.y*va.y + va.z*va.z + va.w*va.w;
    __shared__ float red[8];
    __shared__ float bc;
    ss = warpReduceSum(ss);
    if ((threadIdx.x & 31) == 0) red[threadIdx.x >> 5] = ss;
    __syncthreads();
    if (threadIdx.x == 0) {
        float s = 0.f;
#pragma unroll
        for (int i = 0; i < 8; i++) s += red[i];
        bc = rsqrtf(s / (float)DD + RMS_EPS);
    }
    __syncthreads();
    float r = bc;
    float4 wv = *reinterpret_cast<const float4*>(w + d);
    float4 ov;
    ov.x = va.x*r*wv.x; ov.y = va.y*r*wv.y;
    ov.z = va.z*r*wv.z; ov.w = va.w*r*wv.w;
    *reinterpret_cast<float4*>(out + (long)t*DD + d) = ov;
}

__global__ void qk_rope_kernel(float* __restrict__ buf, const float* __restrict__ nw,
                               const int* __restrict__ pos_ids, int nheads, int rowstride)
{
    int gw = (blockIdx.x * blockDim.x + threadIdx.x) >> 5;
    int lane = threadIdx.x & 31;
    int t = gw / nheads;
    int hh = gw - t * nheads;
    if (t >= TT) return;
    float* p = buf + (long)t * rowstride + hh * HDIM;
    float v0 = p[lane], v1 = p[lane + 32];
    float ss = warpReduceSum(v0*v0 + v1*v1);
    float r = rsqrtf(ss / 64.f + RMS_EPS);
    v0 *= r * nw[lane];
    v1 *= r * nw[lane + 32];
    float inv_freq = (float)pow(1000000.0, -(double)lane / 32.0);
    float ang = (float)pos_ids[t] * inv_freq;
    float c, s;
    sincosf(ang, &s, &c);
    p[lane]      = v0 * c - v1 * s;
    p[lane + 32] = v1 * c + v0 * s;
}

// single-pass softmax: row resident in registers (4 floats/thread)
__global__ void softmax_kernel(float* __restrict__ scores)
{
    long z = blockIdx.y;
    int i = blockIdx.x;
    float* row = scores + (z * SS + i) * (long)SS;
    int valid = i + 1;
    int j0 = threadIdx.x * 4;
    float4 v = *reinterpret_cast<float4*>(row + j0);
    __shared__ float red[8];
    __shared__ float bc;

    float m = -1e30f;
    if (j0+0 < valid) m = fmaxf(m, v.x);
    if (j0+1 < valid) m = fmaxf(m, v.y);
    if (j0+2 < valid) m = fmaxf(m, v.z);
    if (j0+3 < valid) m = fmaxf(m, v.w);
#pragma unroll
    for (int o = 16; o; o >>= 1) m = fmaxf(m, __shfl_xor_sync(0xffffffffu, m, o));
    if ((threadIdx.x & 31) == 0) red[threadIdx.x >> 5] = m;
    __syncthreads();
    if (threadIdx.x == 0) {
        float mm = -1e30f;
#pragma unroll
        for (int i2 = 0; i2 < 8; i2++) mm = fmaxf(mm, red[i2]);
        bc = mm;
    }
    __syncthreads();
    m = bc;

    float4 e;
    e.x = (j0+0 < valid) ? expf(v.x - m) : 0.f;
    e.y = (j0+1 < valid) ? expf(v.y - m) : 0.f;
    e.z = (j0+2 < valid) ? expf(v.z - m) : 0.f;
    e.w = (j0+3 < valid) ? expf(v.w - m) : 0.f;
    float s = e.x + e.y + e.z + e.w;
    s = warpReduceSum(s);
    if ((threadIdx.x & 31) == 0) red[threadIdx.x >> 5] = s;
    __syncthreads();
    if (threadIdx.x == 0) {
        float t = 0.f;
#pragma unroll
        for (int i2 = 0; i2 < 8; i2++) t += red[i2];
        bc = t;
    }
    __syncthreads();
    float inv = 1.f / bc;
    e.x *= inv; e.y *= inv; e.z *= inv; e.w *= inv;
    *reinterpret_cast<float4*>(row + j0) = e;
}

__global__ void router_kernel(const float* __restrict__ h, const float* __restrict__ rw,
                              float* __restrict__ lg)
{
    int t = blockIdx.x;
    __shared__ float sh[DD];
    for (int d = threadIdx.x; d < DD; d += 256) sh[d] = h[(long)t * DD + d];
    __syncthreads();
    int w = threadIdx.x >> 5, lane = threadIdx.x & 31;
    float s = 0.f;
    for (int d = lane; d < DD; d += 32) s += sh[d] * rw[d * EE + w];
    s = warpReduceSum(s);
    if (lane == 0) lg[t * EE + w] = s;
}

__global__ void assign_kernel(const float* __restrict__ lg, int* __restrict__ cnt,
                              int* __restrict__ ptok, int* __restrict__ ppair,
                              float* __restrict__ pw)
{
    int t = blockIdx.x * blockDim.x + threadIdx.x;
    if (t >= TT) return;
    float l1 = -1e30f, l2 = -1e30f;
    int i1 = 0, i2 = 0;
#pragma unroll
    for (int e = 0; e < EE; e++) {
        float v = lg[t * EE + e];
        if (v > l1) { l2 = l1; i2 = i1; l1 = v; i1 = e; }
        else if (v > l2) { l2 = v; i2 = e; }
    }
    float e2 = expf(l2 - l1);
    float w1 = 1.f / (1.f + e2);
    float w2 = e2 / (1.f + e2);
    int p = atomicAdd(&cnt[i1], 1);
    ptok[i1 * CAP + p] = t;  ppair[i1 * CAP + p] = 2 * t;
    p = atomicAdd(&cnt[i2], 1);
    ptok[i2 * CAP + p] = t;  ppair[i2 * CAP + p] = 2 * t + 1;
    pw[2 * t] = w1;  pw[2 * t + 1] = w2;
}

__global__ void silu_mul_kernel(float* __restrict__ g, const float* __restrict__ u)
{
    long i = (long)blockIdx.x * blockDim.x + threadIdx.x;
    float gv = g[i];
    float sg = gv / (1.f + expf(-gv));
    g[i] = sg * u[i];
}

__global__ void combine_kernel(float* __restrict__ x, const float* __restrict__ y,
                               const float* __restrict__ pw)
{
    int t = blockIdx.x;
    float w0 = pw[2 * t], w1 = pw[2 * t + 1];
    int d = threadIdx.x * 4;
    float4 a  = *reinterpret_cast<float4*>(x + (long)t*DD + d);
    float4 y0 = *reinterpret_cast<const float4*>(y + (long)(2*t)*DD + d);
    float4 y1 = *reinterpret_cast<const float4*>(y + (long)(2*t+1)*DD + d);
    a.x += w0*y0.x + w1*y1.x;
    a.y += w0*y0.y + w1*y1.y;
    a.z += w0*y0.z + w1*y1.z;
    a.w += w0*y0.w + w1*y1.w;
    *reinterpret_cast<float4*>(x + (long)t*DD + d) = a;
}

// ---------------- launch ----------------
extern "C" void kernel_launch(void* const* d_in, const int* in_sizes, int n_in,
                              void* d_out, int out_size)
{
    const int*   token_ids = (const int*)  d_in[0];
    const int*   pos_ids   = (const int*)  d_in[1];
    const float* tok_emb   = (const float*)d_in[2];
    const float* attn_norm = (const float*)d_in[3];
    const float* wq        = (const float*)d_in[4];
    const float* wk        = (const float*)d_in[5];
    const float* wv        = (const float*)d_in[6];
    const float* qn        = (const float*)d_in[7];
    const float* kn        = (const float*)d_in[8];
    const float* wo        = (const float*)d_in[9];
    const float* ffn_norm  = (const float*)d_in[10];
    const float* router_w  = (const float*)d_in[11];
    const float* gate_w    = (const float*)d_in[12];
    const float* up_w      = (const float*)d_in[13];
    const float* down_w    = (const float*)d_in[14];
    const float* fin_norm  = (const float*)d_in[15];

    float *x, *h, *q, *k, *v, *sc, *o, *gt, *up, *y, *rlog, *pw;
    int *cnt, *ptok, *ppair;
    cudaGetSymbolAddress((void**)&x,  g_x);
    cudaGetSymbolAddress((void**)&h,  g_h);
    cudaGetSymbolAddress((void**)&q,  g_q);
    cudaGetSymbolAddress((void**)&k,  g_k);
    cudaGetSymbolAddress((void**)&v,  g_v);
    cudaGetSymbolAddress((void**)&sc, g_scores);
    cudaGetSymbolAddress((void**)&o,  g_o);
    cudaGetSymbolAddress((void**)&gt, g_gate);
    cudaGetSymbolAddress((void**)&up, g_up);
    cudaGetSymbolAddress((void**)&y,  g_y);
    cudaGetSymbolAddress((void**)&rlog, g_rlog);
    cudaGetSymbolAddress((void**)&pw,   g_pairw);
    cudaGetSymbolAddress((void**)&cnt,  g_cnt);
    cudaGetSymbolAddress((void**)&ptok, g_ptok);
    cudaGetSymbolAddress((void**)&ppair,g_ppair);

    embed_kernel<<<TT, 256>>>(token_ids, tok_emb, x);

    for (int l = 0; l < LL; l++) {
        // ---- attention ----
        rmsnorm_kernel<<<TT, 256>>>(x, attn_norm + (long)l*DD, h);
        qkv_gemm<<<dim3(12, TT/BM), 256>>>(h, wq + (long)l*DD*QD, wk + (long)l*DD*KD,
                                           wv + (long)l*DD*KD, q, k, v);
        qk_rope_kernel<<<TT*HH/8, 256>>>(q, qn + (long)l*HDIM, pos_ids, HH, QD);
        qk_rope_kernel<<<TT*KVH/8, 256>>>(k, kn + (long)l*HDIM, pos_ids, KVH, KD);
        attn_scores_mma<<<dim3(SS/BN, SS/BM, BB*HH), 256>>>(q, k, sc);
        softmax_kernel<<<dim3(SS, BB*HH), 256>>>(sc);
        attn_pv_mma<<<dim3(1, SS/BM, BB*HH), 256>>>(sc, v, o);
        mma_gemm<false,true><<<dim3(DD/BN, TT/BM), 256>>>(o, wo + (long)l*QD*DD, x, TT, DD, QD, QD, DD, DD);

        // ---- MoE FFN ----
        rmsnorm_kernel<<<TT, 256>>>(x, ffn_norm + (long)l*DD, h);
        router_kernel<<<TT, 256>>>(h, router_w + (long)l*DD*EE, rlog);
        cudaMemsetAsync(cnt, 0, EE * sizeof(int));
        assign_kernel<<<TT/256, 256>>>(rlog, cnt, ptok, ppair, pw);
        moe_mma_gemm<<<dim3(FF/BN, 2*TT/BM, EE), 256>>>(
            h, gate_w + (long)l*EE*DD*FF, (long)DD*FF, gt, FF, DD, DD, FF, FF, ptok, ppair, cnt);
        moe_mma_gemm<<<dim3(FF/BN, 2*TT/BM, EE), 256>>>(
            h, up_w + (long)l*EE*DD*FF, (long)DD*FF, up, FF, DD, DD, FF, FF, ptok, ppair, cnt);
        silu_mul_kernel<<<(2*TT*FF)/256, 256>>>(gt, up);
        moe_mma_gemm<<<dim3(DD/BN, 2*TT/BM, EE), 256>>>(
            gt, down_w + (long)l*EE*FF*DD, (long)FF*DD, y, DD, FF, FF, DD, DD, ppair, ppair, cnt);
        combine_kernel<<<TT, 256>>>(x, y, pw);
    }

    // ---- final norm + tied lm_head ----
    rmsnorm_kernel<<<TT, 256>>>(x, fin_norm, h);
    mma_gemm<true,false><<<dim3(VV/BN, TT/BM), 256>>>(
        h, tok_emb, (float*)d_out, TT, VV, DD, DD, DD, VV);
}

// round 11
// speedup vs baseline: 3.8714x; 1.1738x over previous
#include <cuda_runtime.h>
#include <cuda_bf16.h>
#include <cstdint>
#include <math.h>

// ---------------- model constants ----------------
#define TT 2048      // B*S tokens
#define BB 2
#define SS 1024
#define DD 1024
#define HH 16
#define KVH 4
#define HDIM 64
#define LL 4
#define EE 8
#define FF 1024
#define VV 32000
#define CAP 4096
#define QD (HH*HDIM)   // 1024
#define KD (KVH*HDIM)  // 256
#define ATT_SCALE 0.125f
#define RMS_EPS 1e-6f
// -log2(1e6)/32
#define ROPE_L2 (-0.62286151779138045f)

// ---------------- scratch ----------------
__device__ float g_x[TT*DD];
__device__ float g_h[TT*DD];
__device__ float g_q[TT*QD];
__device__ float g_k[TT*KD];
__device__ float g_v[TT*KD];
__device__ float g_scores[(long)BB*HH*SS*SS];
__device__ float g_o[TT*QD];
__device__ float g_gate[2*TT*FF];
__device__ float g_up[2*TT*FF];
__device__ float g_y[2*TT*DD];
__device__ float g_rlog[TT*EE];
__device__ float g_pairw[2*TT];
__device__ int   g_cnt[EE];
__device__ int   g_ptok[EE*CAP];
__device__ int   g_ppair[EE*CAP];

__device__ __forceinline__ float warpReduceSum(float v){
#pragma unroll
    for (int o = 16; o; o >>= 1) v += __shfl_xor_sync(0xffffffffu, v, o);
    return v;
}

// split two fp32 into packed bf16 hi-pair and lo-pair (low half = first elem)
__device__ __forceinline__ void split_pack(float x0, float x1, uint32_t& h, uint32_t& l){
    __nv_bfloat16 h0 = __float2bfloat16(x0);
    __nv_bfloat16 h1 = __float2bfloat16(x1);
    __nv_bfloat16 l0 = __float2bfloat16(x0 - __bfloat162float(h0));
    __nv_bfloat16 l1 = __float2bfloat16(x1 - __bfloat162float(h1));
    __nv_bfloat162 hh = __halves2bfloat162(h0, h1);
    __nv_bfloat162 ll = __halves2bfloat162(l0, l1);
    h = *reinterpret_cast<uint32_t*>(&hh);
    l = *reinterpret_cast<uint32_t*>(&ll);
}

// ============== bf16x2 (3-product) mma GEMM: 128x128 block, BK=16, 8 warps ==============
constexpr int BM = 128, BN = 128, BK = 16;
constexpr int SAK  = 12;   // u32 stride for [row][kpair] planes (8 pairs + pad, conflict-free)
constexpr int BNST = 136;  // u32 stride for [kpair][n] planes (non-TB B)
constexpr int PLSZ = 1536; // u32 per plane (covers 128*12 and 8*136)

#define MMAB(d, a, b) \
  asm volatile("mma.sync.aligned.m16n8k16.row.col.f32.bf16.bf16.f32 " \
    "{%0,%1,%2,%3},{%4,%5,%6,%7},{%8,%9},{%0,%1,%2,%3};" \
    : "+f"(d[0]),"+f"(d[1]),"+f"(d[2]),"+f"(d[3]) \
    : "r"(a[0]),"r"(a[1]),"r"(a[2]),"r"(a[3]),"r"(b[0]),"r"(b[1]))

template<bool TB, bool ADD, bool GATHER>
__device__ __forceinline__ void mma_body(
    const float* __restrict__ A, const float* __restrict__ B, float* __restrict__ C,
    int M, int N, int K, int lda, int ldb, int ldc,
    int m0, int n0, float alpha,
    const int* __restrict__ aidx, const int* __restrict__ cidx)
{
    // layout: [buf][plane(hi=0,lo=1)][PLSZ]
    __shared__ uint32_t sA[2][2][PLSZ];
    __shared__ uint32_t sB[2][2][PLSZ];
    const int tid = threadIdx.x;
    const int lane = tid & 31, wid = tid >> 5;
    const int wm = wid & 1, wn = wid >> 1;       // 2 x 4 warps, 64x32 tiles
    const int g = lane >> 2, tq = lane & 3;

    float acc[4][4][4];
#pragma unroll
    for (int mt=0; mt<4; mt++)
#pragma unroll
        for (int nt=0; nt<4; nt++)
#pragma unroll
            for (int i=0;i<4;i++) acc[mt][nt][i]=0.f;

    // ---- global->smem mappings (fixed per thread) ----
    const float* aptr[2]; int aoff[2];   // aoff in u32 units into plane
#pragma unroll
    for (int i=0;i<2;i++){
        int idx = tid + i*256;
        int row = idx>>2, seg=(idx&3)*4;     // seg: k offset (0,4,8,12)
        int m = m0 + row;
        bool ok = m < M;
        int r = ok ? (GATHER ? aidx[m] : m) : 0;
        aptr[i] = ok ? (A + (long)r*lda + seg) : nullptr;
        aoff[i] = row*SAK + seg/2;
    }
    const float* bptrN = nullptr; int boffN = 0;
    const float* bptrT[2] = {nullptr,nullptr}; int boffT[2] = {0,0};
    if (!TB){
        int kp = tid >> 5;              // 0..7
        int nseg = (tid & 31) * 4;      // 0..124
        bool ok = (n0 + nseg) < N;
        bptrN = ok ? (B + (long)(2*kp)*ldb + n0 + nseg) : nullptr;
        boffN = kp*BNST + nseg;
    } else {
#pragma unroll
        for (int i=0;i<2;i++){
            int idx = tid + i*256;
            int n = idx>>2, kseg=(idx&3)*4;
            bool ok = (n0+n) < N;
            bptrT[i] = ok ? (B + (long)(n0+n)*ldb + kseg) : nullptr;
            boffT[i] = n*SAK + kseg/2;
        }
    }

    const float4 Z4 = make_float4(0.f,0.f,0.f,0.f);

    // ---- prologue: fill buffer 0 ----
    {
#pragma unroll
        for (int i=0;i<2;i++){
            float4 v = aptr[i] ? *reinterpret_cast<const float4*>(aptr[i]) : Z4;
            uint32_t h0,l0,h1,l1;
            split_pack(v.x, v.y, h0, l0);
            split_pack(v.z, v.w, h1, l1);
            *reinterpret_cast<uint2*>(&sA[0][0][aoff[i]]) = make_uint2(h0,h1);
            *reinterpret_cast<uint2*>(&sA[0][1][aoff[i]]) = make_uint2(l0,l1);
        }
        if (!TB){
            float4 v0 = bptrN ? *reinterpret_cast<const float4*>(bptrN) : Z4;
            float4 v1 = bptrN ? *reinterpret_cast<const float4*>(bptrN + ldb) : Z4;
            uint32_t h0,l0,h1,l1,h2,l2,h3,l3;
            split_pack(v0.x, v1.x, h0, l0);
            split_pack(v0.y, v1.y, h1, l1);
            split_pack(v0.z, v1.z, h2, l2);
            split_pack(v0.w, v1.w, h3, l3);
            *reinterpret_cast<uint4*>(&sB[0][0][boffN]) = make_uint4(h0,h1,h2,h3);
            *reinterpret_cast<uint4*>(&sB[0][1][boffN]) = make_uint4(l0,l1,l2,l3);
        } else {
#pragma unroll
            for (int i=0;i<2;i++){
                float4 v = bptrT[i] ? *reinterpret_cast<const float4*>(bptrT[i]) : Z4;
                uint32_t h0,l0,h1,l1;
                split_pack(v.x, v.y, h0, l0);
                split_pack(v.z, v.w, h1, l1);
                *reinterpret_cast<uint2*>(&sB[0][0][boffT[i]]) = make_uint2(h0,h1);
                *reinterpret_cast<uint2*>(&sB[0][1][boffT[i]]) = make_uint2(l0,l1);
            }
        }
    }
    __syncthreads();

    const int nk = K / BK;
    for (int kb = 0; kb < nk; kb++){
        const int cur = kb & 1;
        float4 pa[2], pb0, pb1, pbt[2];
        if (kb+1 < nk){
#pragma unroll
            for (int i=0;i<2;i++)
                pa[i] = aptr[i] ? *reinterpret_cast<const float4*>(aptr[i] + (kb+1)*BK) : Z4;
            if (!TB){
                long adv = (long)(kb+1)*BK*ldb;
                pb0 = bptrN ? *reinterpret_cast<const float4*>(bptrN + adv) : Z4;
                pb1 = bptrN ? *reinterpret_cast<const float4*>(bptrN + adv + ldb) : Z4;
            } else {
#pragma unroll
                for (int i=0;i<2;i++)
                    pbt[i] = bptrT[i] ? *reinterpret_cast<const float4*>(bptrT[i] + (kb+1)*BK) : Z4;
            }
        }

        const uint32_t* Ah = sA[cur][0];
        const uint32_t* Al = sA[cur][1];
        const uint32_t* Bh = sB[cur][0];
        const uint32_t* Bl = sB[cur][1];

        uint32_t ah[4][4], al[4][4], bh[4][2], bl[4][2];
#pragma unroll
        for (int mt=0; mt<4; mt++){
            int r = wm*64 + mt*16 + g;
            int o0 = r*SAK + tq, o1 = (r+8)*SAK + tq;
            ah[mt][0]=Ah[o0];   ah[mt][1]=Ah[o1];
            ah[mt][2]=Ah[o0+4]; ah[mt][3]=Ah[o1+4];
            al[mt][0]=Al[o0];   al[mt][1]=Al[o1];
            al[mt][2]=Al[o0+4]; al[mt][3]=Al[o1+4];
        }
#pragma unroll
        for (int nt=0; nt<4; nt++){
            if (!TB){
                int n = wn*32 + nt*8 + g;
                int o0 = tq*BNST + n;
                int o1 = (tq+4)*BNST + n;
                bh[nt][0]=Bh[o0]; bh[nt][1]=Bh[o1];
                bl[nt][0]=Bl[o0]; bl[nt][1]=Bl[o1];
            } else {
                int n = wn*32 + nt*8 + g;
                int o0 = n*SAK + tq, o1 = n*SAK + tq + 4;
                bh[nt][0]=Bh[o0]; bh[nt][1]=Bh[o1];
                bl[nt][0]=Bl[o0]; bl[nt][1]=Bl[o1];
            }
        }
#pragma unroll
        for (int mt=0; mt<4; mt++)
#pragma unroll
            for (int nt=0; nt<4; nt++){
                MMAB(acc[mt][nt], al[mt], bh[nt]);   // lo*hi
                MMAB(acc[mt][nt], ah[mt], bl[nt]);   // hi*lo
                MMAB(acc[mt][nt], ah[mt], bh[nt]);   // hi*hi
            }

        if (kb+1 < nk){
            const int nxt = 1-cur;
#pragma unroll
            for (int i=0;i<2;i++){
                float4 v = pa[i];
                uint32_t h0,l0,h1,l1;
                split_pack(v.x, v.y, h0, l0);
                split_pack(v.z, v.w, h1, l1);
                *reinterpret_cast<uint2*>(&sA[nxt][0][aoff[i]]) = make_uint2(h0,h1);
                *reinterpret_cast<uint2*>(&sA[nxt][1][aoff[i]]) = make_uint2(l0,l1);
            }
            if (!TB){
                uint32_t h0,l0,h1,l1,h2,l2,h3,l3;
                split_pack(pb0.x, pb1.x, h0, l0);
                split_pack(pb0.y, pb1.y, h1, l1);
                split_pack(pb0.z, pb1.z, h2, l2);
                split_pack(pb0.w, pb1.w, h3, l3);
                *reinterpret_cast<uint4*>(&sB[nxt][0][boffN]) = make_uint4(h0,h1,h2,h3);
                *reinterpret_cast<uint4*>(&sB[nxt][1][boffN]) = make_uint4(l0,l1,l2,l3);
            } else {
#pragma unroll
                for (int i=0;i<2;i++){
                    float4 v = pbt[i];
                    uint32_t h0,l0,h1,l1;
                    split_pack(v.x, v.y, h0, l0);
                    split_pack(v.z, v.w, h1, l1);
                    *reinterpret_cast<uint2*>(&sB[nxt][0][boffT[i]]) = make_uint2(h0,h1);
                    *reinterpret_cast<uint2*>(&sB[nxt][1][boffT[i]]) = make_uint2(l0,l1);
                }
            }
            __syncthreads();
        }
    }

    // ---- epilogue ----
#pragma unroll
    for (int mt=0; mt<4; mt++){
        int r0 = m0 + wm*64 + mt*16 + g;
        int r1 = r0 + 8;
#pragma unroll
        for (int rr=0; rr<2; rr++){
            int m = rr ? r1 : r0;
            if (m >= M) continue;
            long crow = GATHER ? (long)cidx[m] : (long)m;
            float* cp = C + crow*ldc;
#pragma unroll
            for (int nt=0; nt<4; nt++){
                int c0 = n0 + wn*32 + nt*8 + tq*2;
                if (c0 >= N) continue;
                float v0 = acc[mt][nt][rr*2+0]*alpha;
                float v1 = acc[mt][nt][rr*2+1]*alpha;
                if (ADD){ cp[c0] += v0; cp[c0+1] += v1; }
                else { *reinterpret_cast<float2*>(cp + c0) = make_float2(v0, v1); }
            }
        }
    }
}

template<bool TB, bool ADD>
__global__ void __launch_bounds__(256)
mma_gemm(const float* __restrict__ A, const float* __restrict__ B, float* __restrict__ C,
         int M, int N, int K, int lda, int ldb, int ldc)
{
    mma_body<TB,ADD,false>(A,B,C,M,N,K,lda,ldb,ldc,
                           blockIdx.y*BM, blockIdx.x*BN, 1.f, nullptr, nullptr);
}

// fused QKV: grid (12, TT/BM). x: 0-7 -> Q tiles, 8-9 -> K, 10-11 -> V
__global__ void __launch_bounds__(256)
qkv_gemm(const float* __restrict__ h,
         const float* __restrict__ wq, const float* __restrict__ wk, const float* __restrict__ wv,
         float* __restrict__ q, float* __restrict__ k, float* __restrict__ v)
{
    int bx = blockIdx.x;
    const float* B; float* C; int ldx, N, n0;
    if (bx < 8)       { B = wq; C = q; ldx = QD; N = QD; n0 = bx*128; }
    else if (bx < 10) { B = wk; C = k; ldx = KD; N = KD; n0 = (bx-8)*128; }
    else              { B = wv; C = v; ldx = KD; N = KD; n0 = (bx-10)*128; }
    mma_body<false,false,false>(h, B, C, TT, N, DD, DD, ldx, ldx,
                                blockIdx.y*BM, n0, 1.f, nullptr, nullptr);
}

__global__ void __launch_bounds__(256)
moe_mma_gemm(const float* __restrict__ A, const float* __restrict__ Bbase, long bstride,
             float* __restrict__ C, int N, int K, int lda, int ldb, int ldc,
             const int* __restrict__ aidx, const int* __restrict__ cidx,
             const int* __restrict__ cnt)
{
    int e = blockIdx.z;
    int M = cnt[e];
    int m0 = blockIdx.y * BM;
    if (m0 >= M) return;
    mma_body<false,false,true>(A, Bbase + (long)e*bstride, C, M, N, K, lda, ldb, ldc,
                               m0, blockIdx.x*BN, 1.f, aidx + e*CAP, cidx + e*CAP);
}

__global__ void __launch_bounds__(256)
attn_scores_mma(const float* __restrict__ q, const float* __restrict__ k,
                float* __restrict__ scores)
{
    int z = blockIdx.z;
    int b = z / HH, h = z % HH;
    int m0 = blockIdx.y * BM, n0 = blockIdx.x * BN;
    if (n0 >= m0 + BM) return;   // fully masked causal tile
    const float* A = q + (long)b*SS*QD + h*HDIM;
    const float* B = k + (long)b*SS*KD + (h>>2)*HDIM;
    float* C = scores + (long)z*SS*SS;
    mma_body<true,false,false>(A,B,C, SS,SS,HDIM, QD,KD,SS, m0,n0, ATT_SCALE, nullptr,nullptr);
}

__global__ void __launch_bounds__(256)
attn_pv_mma(const float* __restrict__ scores, const float* __restrict__ v,
            float* __restrict__ o)
{
    int z = blockIdx.z;
    int b = z / HH, h = z % HH;
    const float* A = scores + (long)z*SS*SS;
    const float* B = v + (long)b*SS*KD + (h>>2)*HDIM;
    float* C = o + (long)b*SS*QD + h*HDIM;
    mma_body<false,false,false>(A,B,C, SS,HDIM,SS, SS,KD,QD, blockIdx.y*BM, 0, 1.f, nullptr,nullptr);
}

// ---------------- elementwise / small kernels ----------------
__global__ void embed_kernel(const int* __restrict__ ids, const float* __restrict__ emb,
                             float* __restrict__ x)
{
    int t = blockIdx.x;
    long src = (long)ids[t] * DD;
    int d = threadIdx.x * 4;
    *reinterpret_cast<float4*>(x + (long)t*DD + d) =
        *reinterpret_cast<const float4*>(emb + src + d);
}

__global__ void rmsnorm_kernel(const float* __restrict__ in, const float* __restrict__ w,
                               float* __restrict__ out)
{
    int t = blockIdx.x;
    const float* row = in + (long)t * DD;
    int d = threadIdx.x * 4;
    float4 va = *reinterpret_cast<const float4*>(row + d);
    float ss = va.x*va.x + va.y*va.y + va.z*va.z + va.w*va.w;
    __shared__ float red[8];
    __shared__ float bc;
    ss = warpReduceSum(ss);
    if ((threadIdx.x & 31) == 0) red[threadIdx.x >> 5] = ss;
    __syncthreads();
    if (threadIdx.x == 0) {
        float s = 0.f;
#pragma unroll
        for (int i = 0; i < 8; i++) s += red[i];
        bc = rsqrtf(s / (float)DD + RMS_EPS);
    }
    __syncthreads();
    float r = bc;
    float4 wv = *reinterpret_cast<const float4*>(w + d);
    float4 ov;
    ov.x = va.x*r*wv.x; ov.y = va.y*r*wv.y;
    ov.z = va.z*r*wv.z; ov.w = va.w*r*wv.w;
    *reinterpret_cast<float4*>(out + (long)t*DD + d) = ov;
}

// fused Q+K rope: one warp per (token, head); heads 0..15 -> Q, 16..19 -> K
__global__ void qk_rope_fused_kernel(float* __restrict__ q, float* __restrict__ k,
                                     const float* __restrict__ qnw, const float* __restrict__ knw,
                                     const int* __restrict__ pos_ids)
{
    int gw = (blockIdx.x * blockDim.x + threadIdx.x) >> 5;
    int lane = threadIdx.x & 31;
    int t = gw / (HH + KVH);
    int hh = gw - t * (HH + KVH);
    if (t >= TT) return;
    float* p;
    const float* nw;
    if (hh < HH) { p = q + (long)t * QD + hh * HDIM; nw = qnw; }
    else         { p = k + (long)t * KD + (hh - HH) * HDIM; nw = knw; }
    float v0 = p[lane], v1 = p[lane + 32];
    float ss = warpReduceSum(v0*v0 + v1*v1);
    float r = rsqrtf(ss / 64.f + RMS_EPS);
    v0 *= r * nw[lane];
    v1 *= r * nw[lane + 32];
    float inv_freq = exp2f(ROPE_L2 * (float)lane);
    float ang = (float)pos_ids[t] * inv_freq;
    float c, s;
    __sincosf(ang, &s, &c);
    // __sincosf precision at |ang| up to 1023*1.0 -> fine (|ang|<=1023); use precise path:
    sincosf(ang, &s, &c);
    p[lane]      = v0 * c - v1 * s;
    p[lane + 32] = v1 * c + v0 * s;
}

// single-pass softmax: row resident in registers (4 floats/thread)
__global__ void softmax_kernel(float* __restrict__ scores)
{
    long z = blockIdx.y;
    int i = blockIdx.x;
    float* row = scores + (z * SS + i) * (long)SS;
    int valid = i + 1;
    int j0 = threadIdx.x * 4;
    float4 v = *reinterpret_cast<float4*>(row + j0);
    __shared__ float red[8];
    __shared__ float bc;

    float m = -1e30f;
    if (j0+0 < valid) m = fmaxf(m, v.x);
    if (j0+1 < valid) m = fmaxf(m, v.y);
    if (j0+2 < valid) m = fmaxf(m, v.z);
    if (j0+3 < valid) m = fmaxf(m, v.w);
#pragma unroll
    for (int o = 16; o; o >>= 1) m = fmaxf(m, __shfl_xor_sync(0xffffffffu, m, o));
    if ((threadIdx.x & 31) == 0) red[threadIdx.x >> 5] = m;
    __syncthreads();
    if (threadIdx.x == 0) {
        float mm = -1e30f;
#pragma unroll
        for (int i2 = 0; i2 < 8; i2++) mm = fmaxf(mm, red[i2]);
        bc = mm;
    }
    __syncthreads();
    m = bc;

    float4 e;
    e.x = (j0+0 < valid) ? expf(v.x - m) : 0.f;
    e.y = (j0+1 < valid) ? expf(v.y - m) : 0.f;
    e.z = (j0+2 < valid) ? expf(v.z - m) : 0.f;
    e.w = (j0+3 < valid) ? expf(v.w - m) : 0.f;
    float s = e.x + e.y + e.z + e.w;
    s = warpReduceSum(s);
    if ((threadIdx.x & 31) == 0) red[threadIdx.x >> 5] = s;
    __syncthreads();
    if (threadIdx.x == 0) {
        float t = 0.f;
#pragma unroll
        for (int i2 = 0; i2 < 8; i2++) t += red[i2];
        bc = t;
    }
    __syncthreads();
    float inv = 1.f / bc;
    e.x *= inv; e.y *= inv; e.z *= inv; e.w *= inv;
    *reinterpret_cast<float4*>(row + j0) = e;
}

__global__ void router_kernel(const float* __restrict__ h, const float* __restrict__ rw,
                              float* __restrict__ lg)
{
    int t = blockIdx.x;
    __shared__ float sh[DD];
    for (int d = threadIdx.x; d < DD; d += 256) sh[d] = h[(long)t * DD + d];
    __syncthreads();
    int w = threadIdx.x >> 5, lane = threadIdx.x & 31;
    float s = 0.f;
    for (int d = lane; d < DD; d += 32) s += sh[d] * rw[d * EE + w];
    s = warpReduceSum(s);
    if (lane == 0) lg[t * EE + w] = s;
}

__global__ void assign_kernel(const float* __restrict__ lg, int* __restrict__ cnt,
                              int* __restrict__ ptok, int* __restrict__ ppair,
                              float* __restrict__ pw)
{
    int t = blockIdx.x * blockDim.x + threadIdx.x;
    if (t >= TT) return;
    float l1 = -1e30f, l2 = -1e30f;
    int i1 = 0, i2 = 0;
#pragma unroll
    for (int e = 0; e < EE; e++) {
        float v = lg[t * EE + e];
        if (v > l1) { l2 = l1; i2 = i1; l1 = v; i1 = e; }
        else if (v > l2) { l2 = v; i2 = e; }
    }
    float e2 = expf(l2 - l1);
    float w1 = 1.f / (1.f + e2);
    float w2 = e2 / (1.f + e2);
    int p = atomicAdd(&cnt[i1], 1);
    ptok[i1 * CAP + p] = t;  ppair[i1 * CAP + p] = 2 * t;
    p = atomicAdd(&cnt[i2], 1);
    ptok[i2 * CAP + p] = t;  ppair[i2 * CAP + p] = 2 * t + 1;
    pw[2 * t] = w1;  pw[2 * t + 1] = w2;
}

__global__ void silu_mul_kernel(float* __restrict__ g, const float* __restrict__ u)
{
    long i = (long)blockIdx.x * blockDim.x + threadIdx.x;
    float gv = g[i];
    float sg = gv / (1.f + expf(-gv));
    g[i] = sg * u[i];
}

__global__ void combine_kernel(float* __restrict__ x, const float* __restrict__ y,
                               const float* __restrict__ pw)
{
    int t = blockIdx.x;
    float w0 = pw[2 * t], w1 = pw[2 * t + 1];
    int d = threadIdx.x * 4;
    float4 a  = *reinterpret_cast<float4*>(x + (long)t*DD + d);
    float4 y0 = *reinterpret_cast<const float4*>(y + (long)(2*t)*DD + d);
    float4 y1 = *reinterpret_cast<const float4*>(y + (long)(2*t+1)*DD + d);
    a.x += w0*y0.x + w1*y1.x;
    a.y += w0*y0.y + w1*y1.y;
    a.z += w0*y0.z + w1*y1.z;
    a.w += w0*y0.w + w1*y1.w;
    *reinterpret_cast<float4*>(x + (long)t*DD + d) = a;
}

// ---------------- launch ----------------
extern "C" void kernel_launch(void* const* d_in, const int* in_sizes, int n_in,
                              void* d_out, int out_size)
{
    const int*   token_ids = (const int*)  d_in[0];
    const int*   pos_ids   = (const int*)  d_in[1];
    const float* tok_emb   = (const float*)d_in[2];
    const float* attn_norm = (const float*)d_in[3];
    const float* wq        = (const float*)d_in[4];
    const float* wk        = (const float*)d_in[5];
    const float* wv        = (const float*)d_in[6];
    const float* qn        = (const float*)d_in[7];
    const float* kn        = (const float*)d_in[8];
    const float* wo        = (const float*)d_in[9];
    const float* ffn_norm  = (const float*)d_in[10];
    const float* router_w  = (const float*)d_in[11];
    const float* gate_w    = (const float*)d_in[12];
    const float* up_w      = (const float*)d_in[13];
    const float* down_w    = (const float*)d_in[14];
    const float* fin_norm  = (const float*)d_in[15];

    float *x, *h, *q, *k, *v, *sc, *o, *gt, *up, *y, *rlog, *pw;
    int *cnt, *ptok, *ppair;
    cudaGetSymbolAddress((void**)&x,  g_x);
    cudaGetSymbolAddress((void**)&h,  g_h);
    cudaGetSymbolAddress((void**)&q,  g_q);
    cudaGetSymbolAddress((void**)&k,  g_k);
    cudaGetSymbolAddress((void**)&v,  g_v);
    cudaGetSymbolAddress((void**)&sc, g_scores);
    cudaGetSymbolAddress((void**)&o,  g_o);
    cudaGetSymbolAddress((void**)&gt, g_gate);
    cudaGetSymbolAddress((void**)&up, g_up);
    cudaGetSymbolAddress((void**)&y,  g_y);
    cudaGetSymbolAddress((void**)&rlog, g_rlog);
    cudaGetSymbolAddress((void**)&pw,   g_pairw);
    cudaGetSymbolAddress((void**)&cnt,  g_cnt);
    cudaGetSymbolAddress((void**)&ptok, g_ptok);
    cudaGetSymbolAddress((void**)&ppair,g_ppair);

    embed_kernel<<<TT, 256>>>(token_ids, tok_emb, x);

    for (int l = 0; l < LL; l++) {
        // ---- attention ----
        rmsnorm_kernel<<<TT, 256>>>(x, attn_norm + (long)l*DD, h);
        qkv_gemm<<<dim3(12, TT/BM), 256>>>(h, wq + (long)l*DD*QD, wk + (long)l*DD*KD,
                                           wv + (long)l*DD*KD, q, k, v);
        qk_rope_fused_kernel<<<TT*(HH+KVH)/8, 256>>>(q, k, qn + (long)l*HDIM,
                                                     kn + (long)l*HDIM, pos_ids);
        attn_scores_mma<<<dim3(SS/BN, SS/BM, BB*HH), 256>>>(q, k, sc);
        softmax_kernel<<<dim3(SS, BB*HH), 256>>>(sc);
        attn_pv_mma<<<dim3(1, SS/BM, BB*HH), 256>>>(sc, v, o);
        mma_gemm<false,true><<<dim3(DD/BN, TT/BM), 256>>>(o, wo + (long)l*QD*DD, x, TT, DD, QD, QD, DD, DD);

        // ---- MoE FFN ----
        rmsnorm_kernel<<<TT, 256>>>(x, ffn_norm + (long)l*DD, h);
        router_kernel<<<TT, 256>>>(h, router_w + (long)l*DD*EE, rlog);
        cudaMemsetAsync(cnt, 0, EE * sizeof(int));
        assign_kernel<<<TT/256, 256>>>(rlog, cnt, ptok, ppair, pw);
        moe_mma_gemm<<<dim3(FF/BN, 2*TT/BM, EE), 256>>>(
            h, gate_w + (long)l*EE*DD*FF, (long)DD*FF, gt, FF, DD, DD, FF, FF, ptok, ppair, cnt);
        moe_mma_gemm<<<dim3(FF/BN, 2*TT/BM, EE), 256>>>(
            h, up_w + (long)l*EE*DD*FF, (long)DD*FF, up, FF, DD, DD, FF, FF, ptok, ppair, cnt);
        silu_mul_kernel<<<(2*TT*FF)/256, 256>>>(gt, up);
        moe_mma_gemm<<<dim3(DD/BN, 2*TT/BM, EE), 256>>>(
            gt, down_w + (long)l*EE*FF*DD, (long)FF*DD, y, DD, FF, FF, DD, DD, ppair, ppair, cnt);
        combine_kernel<<<TT, 256>>>(x, y, pw);
    }

    // ---- final norm + tied lm_head ----
    rmsnorm_kernel<<<TT, 256>>>(x, fin_norm, h);
    mma_gemm<true,false><<<dim3(VV/BN, TT/BM), 256>>>(
        h, tok_emb, (float*)d_out, TT, VV, DD, DD, DD, VV);
}

// round 14
// speedup vs baseline: 5.3552x; 1.3833x over previous
#include <cuda_runtime.h>
#include <cuda_bf16.h>
#include <cstdint>
#include <math.h>

// ---------------- model constants ----------------
#define TT 2048      // B*S tokens
#define BB 2
#define SS 1024
#define DD 1024
#define HH 16
#define KVH 4
#define HDIM 64
#define LL 4
#define EE 8
#define FF 1024
#define VV 32000
#define CAP 4096
#define QD (HH*HDIM)   // 1024
#define KD (KVH*HDIM)  // 256
#define ATT_SCALE 0.125f
#define RMS_EPS 1e-6f
// -log2(1e6)/32
#define ROPE_L2 (-0.62286151779138045f)

// ---------------- scratch ----------------
__device__ float g_x[TT*DD];
__device__ float g_h[TT*DD];
__device__ float g_q[TT*QD];
__device__ float g_k[TT*KD];
__device__ float g_v[TT*KD];
__device__ float g_scores[(long)BB*HH*SS*SS];
__device__ float g_o[TT*QD];
__device__ float g_gate[2*TT*FF];
__device__ float g_up[2*TT*FF];
__device__ float g_y[2*TT*DD];
__device__ float g_rlog[TT*EE];
__device__ float g_pairw[2*TT];
__device__ int   g_cnt[EE];
__device__ int   g_ptok[EE*CAP];
__device__ int   g_ppair[EE*CAP];

__device__ __forceinline__ float warpReduceSum(float v){
#pragma unroll
    for (int o = 16; o; o >>= 1) v += __shfl_xor_sync(0xffffffffu, v, o);
    return v;
}

// split two fp32 into packed bf16 hi-pair and lo-pair (low half = first elem)
__device__ __forceinline__ void split_pack(float x0, float x1, uint32_t& h, uint32_t& l){
    __nv_bfloat16 h0 = __float2bfloat16(x0);
    __nv_bfloat16 h1 = __float2bfloat16(x1);
    __nv_bfloat16 l0 = __float2bfloat16(x0 - __bfloat162float(h0));
    __nv_bfloat16 l1 = __float2bfloat16(x1 - __bfloat162float(h1));
    __nv_bfloat162 hh = __halves2bfloat162(h0, h1);
    __nv_bfloat162 ll = __halves2bfloat162(l0, l1);
    h = *reinterpret_cast<uint32_t*>(&hh);
    l = *reinterpret_cast<uint32_t*>(&ll);
}

__device__ __forceinline__ uint32_t smem_u32addr(const void* p){
    return (uint32_t)__cvta_generic_to_shared(p);
}

// ============== bf16x2 (3-product) mma GEMM, ldmatrix fragments ==============
constexpr int BM = 128, BN = 128, BK = 16;
constexpr int SAK  = 12;   // u32 stride, [row][k] planes (A, TB-B): 8 kpair u32 + 4 pad
constexpr int BST  = 68;   // u32 stride, [k][n] bf16 planes (!TB B): 64 n-u32 + 4 pad
constexpr int PLSZ = 1536; // u32 per plane (128*12=1536; 16*68=1088)
constexpr int PLB  = PLSZ*4; // plane stride in bytes

#define MMAB(d, a, b) \
  asm volatile("mma.sync.aligned.m16n8k16.row.col.f32.bf16.bf16.f32 " \
    "{%0,%1,%2,%3},{%4,%5,%6,%7},{%8,%9},{%0,%1,%2,%3};" \
    : "+f"(d[0]),"+f"(d[1]),"+f"(d[2]),"+f"(d[3]) \
    : "r"(a[0]),"r"(a[1]),"r"(a[2]),"r"(a[3]),"r"(b[0]),"r"(b[1]))

#define LDSM4(R, A) \
  asm volatile("ldmatrix.sync.aligned.m8n8.x4.shared.b16 {%0,%1,%2,%3},[%4];" \
    : "=r"((R)[0]),"=r"((R)[1]),"=r"((R)[2]),"=r"((R)[3]) : "r"(A))
#define LDSM4T(R0,R1,R2,R3, A) \
  asm volatile("ldmatrix.sync.aligned.m8n8.x4.trans.shared.b16 {%0,%1,%2,%3},[%4];" \
    : "=r"(R0),"=r"(R1),"=r"(R2),"=r"(R3) : "r"(A))

template<bool TB, bool ADD, bool GATHER>
__device__ __forceinline__ void mma_body(
    const float* __restrict__ A, const float* __restrict__ B, float* __restrict__ C,
    int M, int N, int K, int lda, int ldb, int ldc,
    int m0, int n0, float alpha,
    const int* __restrict__ aidx, const int* __restrict__ cidx)
{
    // layout: [buf][plane(hi=0,lo=1)][PLSZ]
    __shared__ uint32_t sA[2][2][PLSZ];
    __shared__ uint32_t sB[2][2][PLSZ];
    const int tid = threadIdx.x;
    const int lane = tid & 31, wid = tid >> 5;
    const int wm = wid & 1, wn = wid >> 1;       // 2 x 4 warps, 64x32 tiles
    const int g = lane >> 2, tq = lane & 3;

    float acc[4][4][4];
#pragma unroll
    for (int mt=0; mt<4; mt++)
#pragma unroll
        for (int nt=0; nt<4; nt++)
#pragma unroll
            for (int i=0;i<4;i++) acc[mt][nt][i]=0.f;

    // ---- global->smem mappings (fixed per thread) ----
    const float* aptr[2]; int aoff[2];   // aoff in u32 units into plane
#pragma unroll
    for (int i=0;i<2;i++){
        int idx = tid + i*256;
        int row = idx>>2, seg=(idx&3)*4;     // seg: k offset (0,4,8,12)
        int m = m0 + row;
        bool ok = m < M;
        int r = ok ? (GATHER ? aidx[m] : m) : 0;
        aptr[i] = ok ? (A + (long)r*lda + seg) : nullptr;
        aoff[i] = row*SAK + seg/2;
    }
    // B: !TB: bf16 [k-row][n] layout; thread covers rows {2kp,2kp+1} x 4n
    //    TB : same layout as A ([n-row][kpair])
    const float* bptrN = nullptr; int boffN0 = 0, boffN1 = 0;
    const float* bptrT[2] = {nullptr,nullptr}; int boffT[2] = {0,0};
    if (!TB){
        int kp = tid >> 5;              // 0..7
        int nseg = (tid & 31) * 4;      // 0..124
        bool ok = (n0 + nseg) < N;
        bptrN = ok ? (B + (long)(2*kp)*ldb + n0 + nseg) : nullptr;
        boffN0 = (2*kp)*BST + nseg/2;
        boffN1 = boffN0 + BST;
    } else {
#pragma unroll
        for (int i=0;i<2;i++){
            int idx = tid + i*256;
            int n = idx>>2, kseg=(idx&3)*4;
            bool ok = (n0+n) < N;
            bptrT[i] = ok ? (B + (long)(n0+n)*ldb + kseg) : nullptr;
            boffT[i] = n*SAK + kseg/2;
        }
    }

    // ---- ldmatrix per-lane fragment byte offsets ----
    const int lx = lane & 7;
    const int aFragOff  = ((wm*64 + lx + ((lane>>3)&1)*8)*SAK + ((lane>>4)&1)*4)*4;
    const int bFragOffT = ((wn*32 + lx + ((lane>>4)&1)*8)*SAK + ((lane>>3)&1)*4)*4;
    const int bFragOffN = ((lx + ((lane>>3)&1)*8)*BST + wn*16 + ((lane>>4)&1)*4)*4;

    const float4 Z4 = make_float4(0.f,0.f,0.f,0.f);

    // ---- prologue: fill buffer 0 ----
    {
#pragma unroll
        for (int i=0;i<2;i++){
            float4 v = aptr[i] ? *reinterpret_cast<const float4*>(aptr[i]) : Z4;
            uint32_t h0,l0,h1,l1;
            split_pack(v.x, v.y, h0, l0);
            split_pack(v.z, v.w, h1, l1);
            *reinterpret_cast<uint2*>(&sA[0][0][aoff[i]]) = make_uint2(h0,h1);
            *reinterpret_cast<uint2*>(&sA[0][1][aoff[i]]) = make_uint2(l0,l1);
        }
        if (!TB){
            float4 v0 = bptrN ? *reinterpret_cast<const float4*>(bptrN) : Z4;
            float4 v1 = bptrN ? *reinterpret_cast<const float4*>(bptrN + ldb) : Z4;
            uint32_t h0,l0,h1,l1,h2,l2,h3,l3;
            split_pack(v0.x, v0.y, h0, l0);
            split_pack(v0.z, v0.w, h1, l1);
            split_pack(v1.x, v1.y, h2, l2);
            split_pack(v1.z, v1.w, h3, l3);
            *reinterpret_cast<uint2*>(&sB[0][0][boffN0]) = make_uint2(h0,h1);
            *reinterpret_cast<uint2*>(&sB[0][0][boffN1]) = make_uint2(h2,h3);
            *reinterpret_cast<uint2*>(&sB[0][1][boffN0]) = make_uint2(l0,l1);
            *reinterpret_cast<uint2*>(&sB[0][1][boffN1]) = make_uint2(l2,l3);
        } else {
#pragma unroll
            for (int i=0;i<2;i++){
                float4 v = bptrT[i] ? *reinterpret_cast<const float4*>(bptrT[i]) : Z4;
                uint32_t h0,l0,h1,l1;
                split_pack(v.x, v.y, h0, l0);
                split_pack(v.z, v.w, h1, l1);
                *reinterpret_cast<uint2*>(&sB[0][0][boffT[i]]) = make_uint2(h0,h1);
                *reinterpret_cast<uint2*>(&sB[0][1][boffT[i]]) = make_uint2(l0,l1);
            }
        }
    }
    __syncthreads();

    const int nk = K / BK;
    for (int kb = 0; kb < nk; kb++){
        const int cur = kb & 1;
        float4 pa[2], pb0, pb1, pbt[2];
        if (kb+1 < nk){
#pragma unroll
            for (int i=0;i<2;i++)
                pa[i] = aptr[i] ? *reinterpret_cast<const float4*>(aptr[i] + (kb+1)*BK) : Z4;
            if (!TB){
                long adv = (long)(kb+1)*BK*ldb;
                pb0 = bptrN ? *reinterpret_cast<const float4*>(bptrN + adv) : Z4;
                pb1 = bptrN ? *reinterpret_cast<const float4*>(bptrN + adv + ldb) : Z4;
            } else {
#pragma unroll
                for (int i=0;i<2;i++)
                    pbt[i] = bptrT[i] ? *reinterpret_cast<const float4*>(bptrT[i] + (kb+1)*BK) : Z4;
            }
        }

        // ---- fragment loads via ldmatrix ----
        uint32_t ah[4][4], al[4][4], bh[4][2], bl[4][2];
        {
            uint32_t aH = smem_u32addr(&sA[cur][0][0]) + aFragOff;
#pragma unroll
            for (int mt=0; mt<4; mt++){
                LDSM4(ah[mt], aH + mt*(16*SAK*4));
                LDSM4(al[mt], aH + mt*(16*SAK*4) + PLB);
            }
            if (!TB){
                uint32_t bH = smem_u32addr(&sB[cur][0][0]) + bFragOffN;
#pragma unroll
                for (int ntp=0; ntp<2; ntp++){
                    LDSM4T(bh[2*ntp][0], bh[2*ntp][1], bh[2*ntp+1][0], bh[2*ntp+1][1],
                           bH + ntp*32);
                    LDSM4T(bl[2*ntp][0], bl[2*ntp][1], bl[2*ntp+1][0], bl[2*ntp+1][1],
                           bH + ntp*32 + PLB);
                }
            } else {
                uint32_t bH = smem_u32addr(&sB[cur][0][0]) + bFragOffT;
#pragma unroll
                for (int ntp=0; ntp<2; ntp++){
                    LDSM4T(bh[2*ntp][0], bh[2*ntp][1], bh[2*ntp+1][0], bh[2*ntp+1][1],
                           bH + ntp*(16*SAK*4));
                    // TB path is non-trans (layout matches fragment directly)
                    (void)0;
                }
                // overwrite with correct non-trans loads
#pragma unroll
                for (int ntp=0; ntp<2; ntp++){
                    uint32_t r0,r1,r2,r3;
                    asm volatile("ldmatrix.sync.aligned.m8n8.x4.shared.b16 {%0,%1,%2,%3},[%4];"
                        : "=r"(r0),"=r"(r1),"=r"(r2),"=r"(r3) : "r"(bH + ntp*(16*SAK*4)));
                    bh[2*ntp][0]=r0; bh[2*ntp][1]=r1; bh[2*ntp+1][0]=r2; bh[2*ntp+1][1]=r3;
                    asm volatile("ldmatrix.sync.aligned.m8n8.x4.shared.b16 {%0,%1,%2,%3},[%4];"
                        : "=r"(r0),"=r"(r1),"=r"(r2),"=r"(r3) : "r"(bH + ntp*(16*SAK*4) + PLB));
                    bl[2*ntp][0]=r0; bl[2*ntp][1]=r1; bl[2*ntp+1][0]=r2; bl[2*ntp+1][1]=r3;
                }
            }
        }
#pragma unroll
        for (int mt=0; mt<4; mt++)
#pragma unroll
            for (int nt=0; nt<4; nt++){
                MMAB(acc[mt][nt], al[mt], bh[nt]);   // lo*hi
                MMAB(acc[mt][nt], ah[mt], bl[nt]);   // hi*lo
                MMAB(acc[mt][nt], ah[mt], bh[nt]);   // hi*hi
            }

        if (kb+1 < nk){
            const int nxt = 1-cur;
#pragma unroll
            for (int i=0;i<2;i++){
                float4 v = pa[i];
                uint32_t h0,l0,h1,l1;
                split_pack(v.x, v.y, h0, l0);
                split_pack(v.z, v.w, h1, l1);
                *reinterpret_cast<uint2*>(&sA[nxt][0][aoff[i]]) = make_uint2(h0,h1);
                *reinterpret_cast<uint2*>(&sA[nxt][1][aoff[i]]) = make_uint2(l0,l1);
            }
            if (!TB){
                uint32_t h0,l0,h1,l1,h2,l2,h3,l3;
                split_pack(pb0.x, pb0.y, h0, l0);
                split_pack(pb0.z, pb0.w, h1, l1);
                split_pack(pb1.x, pb1.y, h2, l2);
                split_pack(pb1.z, pb1.w, h3, l3);
                *reinterpret_cast<uint2*>(&sB[nxt][0][boffN0]) = make_uint2(h0,h1);
                *reinterpret_cast<uint2*>(&sB[nxt][0][boffN1]) = make_uint2(h2,h3);
                *reinterpret_cast<uint2*>(&sB[nxt][1][boffN0]) = make_uint2(l0,l1);
                *reinterpret_cast<uint2*>(&sB[nxt][1][boffN1]) = make_uint2(l2,l3);
            } else {
#pragma unroll
                for (int i=0;i<2;i++){
                    float4 v = pbt[i];
                    uint32_t h0,l0,h1,l1;
                    split_pack(v.x, v.y, h0, l0);
                    split_pack(v.z, v.w, h1, l1);
                    *reinterpret_cast<uint2*>(&sB[nxt][0][boffT[i]]) = make_uint2(h0,h1);
                    *reinterpret_cast<uint2*>(&sB[nxt][1][boffT[i]]) = make_uint2(l0,l1);
                }
            }
            __syncthreads();
        }
    }

    // ---- epilogue ----
#pragma unroll
    for (int mt=0; mt<4; mt++){
        int r0 = m0 + wm*64 + mt*16 + g;
        int r1 = r0 + 8;
#pragma unroll
        for (int rr=0; rr<2; rr++){
            int m = rr ? r1 : r0;
            if (m >= M) continue;
            long crow = GATHER ? (long)cidx[m] : (long)m;
            float* cp = C + crow*ldc;
#pragma unroll
            for (int nt=0; nt<4; nt++){
                int c0 = n0 + wn*32 + nt*8 + tq*2;
                if (c0 >= N) continue;
                float v0 = acc[mt][nt][rr*2+0]*alpha;
                float v1 = acc[mt][nt][rr*2+1]*alpha;
                if (ADD){ cp[c0] += v0; cp[c0+1] += v1; }
                else { *reinterpret_cast<float2*>(cp + c0) = make_float2(v0, v1); }
            }
        }
    }
}

template<bool TB, bool ADD>
__global__ void __launch_bounds__(256)
mma_gemm(const float* __restrict__ A, const float* __restrict__ B, float* __restrict__ C,
         int M, int N, int K, int lda, int ldb, int ldc)
{
    mma_body<TB,ADD,false>(A,B,C,M,N,K,lda,ldb,ldc,
                           blockIdx.y*BM, blockIdx.x*BN, 1.f, nullptr, nullptr);
}

// fused QKV: grid (12, TT/BM). x: 0-7 -> Q tiles, 8-9 -> K, 10-11 -> V
__global__ void __launch_bounds__(256)
qkv_gemm(const float* __restrict__ h,
         const float* __restrict__ wq, const float* __restrict__ wk, const float* __restrict__ wv,
         float* __restrict__ q, float* __restrict__ k, float* __restrict__ v)
{
    int bx = blockIdx.x;
    const float* B; float* C; int ldx, N, n0;
    if (bx < 8)       { B = wq; C = q; ldx = QD; N = QD; n0 = bx*128; }
    else if (bx < 10) { B = wk; C = k; ldx = KD; N = KD; n0 = (bx-8)*128; }
    else              { B = wv; C = v; ldx = KD; N = KD; n0 = (bx-10)*128; }
    mma_body<false,false,false>(h, B, C, TT, N, DD, DD, ldx, ldx,
                                blockIdx.y*BM, n0, 1.f, nullptr, nullptr);
}

__global__ void __launch_bounds__(256)
moe_mma_gemm(const float* __restrict__ A, const float* __restrict__ Bbase, long bstride,
             float* __restrict__ C, int N, int K, int lda, int ldb, int ldc,
             const int* __restrict__ aidx, const int* __restrict__ cidx,
             const int* __restrict__ cnt)
{
    int e = blockIdx.z;
    int M = cnt[e];
    int m0 = blockIdx.y * BM;
    if (m0 >= M) return;
    mma_body<false,false,true>(A, Bbase + (long)e*bstride, C, M, N, K, lda, ldb, ldc,
                               m0, blockIdx.x*BN, 1.f, aidx + e*CAP, cidx + e*CAP);
}

__global__ void __launch_bounds__(256)
attn_scores_mma(const float* __restrict__ q, const float* __restrict__ k,
                float* __restrict__ scores)
{
    int z = blockIdx.z;
    int b = z / HH, h = z % HH;
    int m0 = blockIdx.y * BM, n0 = blockIdx.x * BN;
    if (n0 >= m0 + BM) return;   // fully masked causal tile
    const float* A = q + (long)b*SS*QD + h*HDIM;
    const float* B = k + (long)b*SS*KD + (h>>2)*HDIM;
    float* C = scores + (long)z*SS*SS;
    mma_body<true,false,false>(A,B,C, SS,SS,HDIM, QD,KD,SS, m0,n0, ATT_SCALE, nullptr,nullptr);
}

__global__ void __launch_bounds__(256)
attn_pv_mma(const float* __restrict__ scores, const float* __restrict__ v,
            float* __restrict__ o)
{
    int z = blockIdx.z;
    int b = z / HH, h = z % HH;
    int m0 = blockIdx.y * BM;
    const float* A = scores + (long)z*SS*SS;
    const float* B = v + (long)b*SS*KD + (h>>2)*HDIM;
    float* C = o + (long)b*SS*QD + h*HDIM;
    // causal: rows in this block attend only to keys < m0+BM
    mma_body<false,false,false>(A,B,C, SS,HDIM, m0+BM, SS,KD,QD, m0, 0, 1.f, nullptr,nullptr);
}

// ---------------- elementwise / small kernels ----------------
__global__ void embed_kernel(const int* __restrict__ ids, const float* __restrict__ emb,
                             float* __restrict__ x)
{
    int t = blockIdx.x;
    long src = (long)ids[t] * DD;
    int d = threadIdx.x * 4;
    *reinterpret_cast<float4*>(x + (long)t*DD + d) =
        *reinterpret_cast<const float4*>(emb + src + d);
}

__global__ void rmsnorm_kernel(const float* __restrict__ in, const float* __restrict__ w,
                               float* __restrict__ out)
{
    int t = blockIdx.x;
    const float* row = in + (long)t * DD;
    int d = threadIdx.x * 4;
    float4 va = *reinterpret_cast<const float4*>(row + d);
    float ss = va.x*va.x + va.y*va.y + va.z*va.z + va.w*va.w;
    __shared__ float red[8];
    __shared__ float bc;
    ss = warpReduceSum(ss);
    if ((threadIdx.x & 31) == 0) red[threadIdx.x >> 5] = ss;
    __syncthreads();
    if (threadIdx.x == 0) {
        float s = 0.f;
#pragma unroll
        for (int i = 0; i < 8; i++) s += red[i];
        bc = rsqrtf(s / (float)DD + RMS_EPS);
    }
    __syncthreads();
    float r = bc;
    float4 wv = *reinterpret_cast<const float4*>(w + d);
    float4 ov;
    ov.x = va.x*r*wv.x; ov.y = va.y*r*wv.y;
    ov.z = va.z*r*wv.z; ov.w = va.w*r*wv.w;
    *reinterpret_cast<float4*>(out + (long)t*DD + d) = ov;
}

// fused Q+K rope: one warp per (token, head); heads 0..15 -> Q, 16..19 -> K
__global__ void qk_rope_fused_kernel(float* __restrict__ q, float* __restrict__ k,
                                     const float* __restrict__ qnw, const float* __restrict__ knw,
                                     const int* __restrict__ pos_ids)
{
    int gw = (blockIdx.x * blockDim.x + threadIdx.x) >> 5;
    int lane = threadIdx.x & 31;
    int t = gw / (HH + KVH);
    int hh = gw - t * (HH + KVH);
    if (t >= TT) return;
    float* p;
    const float* nw;
    if (hh < HH) { p = q + (long)t * QD + hh * HDIM; nw = qnw; }
    else         { p = k + (long)t * KD + (hh - HH) * HDIM; nw = knw; }
    float v0 = p[lane], v1 = p[lane + 32];
    float ss = warpReduceSum(v0*v0 + v1*v1);
    float r = rsqrtf(ss / 64.f + RMS_EPS);
    v0 *= r * nw[lane];
    v1 *= r * nw[lane + 32];
    float inv_freq = exp2f(ROPE_L2 * (float)lane);
    float ang = (float)pos_ids[t] * inv_freq;
    float c, s;
    sincosf(ang, &s, &c);
    p[lane]      = v0 * c - v1 * s;
    p[lane + 32] = v1 * c + v0 * s;
}

// single-pass softmax: row resident in registers (4 floats/thread)
__global__ void softmax_kernel(float* __restrict__ scores)
{
    long z = blockIdx.y;
    int i = blockIdx.x;
    float* row = scores + (z * SS + i) * (long)SS;
    int valid = i + 1;
    int j0 = threadIdx.x * 4;
    float4 v = *reinterpret_cast<float4*>(row + j0);
    __shared__ float red[8];
    __shared__ float bc;

    float m = -1e30f;
    if (j0+0 < valid) m = fmaxf(m, v.x);
    if (j0+1 < valid) m = fmaxf(m, v.y);
    if (j0+2 < valid) m = fmaxf(m, v.z);
    if (j0+3 < valid) m = fmaxf(m, v.w);
#pragma unroll
    for (int o = 16; o; o >>= 1) m = fmaxf(m, __shfl_xor_sync(0xffffffffu, m, o));
    if ((threadIdx.x & 31) == 0) red[threadIdx.x >> 5] = m;
    __syncthreads();
    if (threadIdx.x == 0) {
        float mm = -1e30f;
#pragma unroll
        for (int i2 = 0; i2 < 8; i2++) mm = fmaxf(mm, red[i2]);
        bc = mm;
    }
    __syncthreads();
    m = bc;

    float4 e;
    e.x = (j0+0 < valid) ? expf(v.x - m) : 0.f;
    e.y = (j0+1 < valid) ? expf(v.y - m) : 0.f;
    e.z = (j0+2 < valid) ? expf(v.z - m) : 0.f;
    e.w = (j0+3 < valid) ? expf(v.w - m) : 0.f;
    float s = e.x + e.y + e.z + e.w;
    s = warpReduceSum(s);
    if ((threadIdx.x & 31) == 0) red[threadIdx.x >> 5] = s;
    __syncthreads();
    if (threadIdx.x == 0) {
        float t = 0.f;
#pragma unroll
        for (int i2 = 0; i2 < 8; i2++) t += red[i2];
        bc = t;
    }
    __syncthreads();
    float inv = 1.f / bc;
    e.x *= inv; e.y *= inv; e.z *= inv; e.w *= inv;
    *reinterpret_cast<float4*>(row + j0) = e;
}

__global__ void router_kernel(const float* __restrict__ h, const float* __restrict__ rw,
                              float* __restrict__ lg)
{
    int t = blockIdx.x;
    __shared__ float sh[DD];
    for (int d = threadIdx.x; d < DD; d += 256) sh[d] = h[(long)t * DD + d];
    __syncthreads();
    int w = threadIdx.x >> 5, lane = threadIdx.x & 31;
    float s = 0.f;
    for (int d = lane; d < DD; d += 32) s += sh[d] * rw[d * EE + w];
    s = warpReduceSum(s);
    if (lane == 0) lg[t * EE + w] = s;
}

__global__ void assign_kernel(const float* __restrict__ lg, int* __restrict__ cnt,
                              int* __restrict__ ptok, int* __restrict__ ppair,
                              float* __restrict__ pw)
{
    int t = blockIdx.x * blockDim.x + threadIdx.x;
    if (t >= TT) return;
    float l1 = -1e30f, l2 = -1e30f;
    int i1 = 0, i2 = 0;
#pragma unroll
    for (int e = 0; e < EE; e++) {
        float v = lg[t * EE + e];
        if (v > l1) { l2 = l1; i2 = i1; l1 = v; i1 = e; }
        else if (v > l2) { l2 = v; i2 = e; }
    }
    float e2 = expf(l2 - l1);
    float w1 = 1.f / (1.f + e2);
    float w2 = e2 / (1.f + e2);
    int p = atomicAdd(&cnt[i1], 1);
    ptok[i1 * CAP + p] = t;  ppair[i1 * CAP + p] = 2 * t;
    p = atomicAdd(&cnt[i2], 1);
    ptok[i2 * CAP + p] = t;  ppair[i2 * CAP + p] = 2 * t + 1;
    pw[2 * t] = w1;  pw[2 * t + 1] = w2;
}

__global__ void silu_mul_kernel(float* __restrict__ g, const float* __restrict__ u)
{
    long i = (long)blockIdx.x * blockDim.x + threadIdx.x;
    float gv = g[i];
    float sg = gv / (1.f + expf(-gv));
    g[i] = sg * u[i];
}

__global__ void combine_kernel(float* __restrict__ x, const float* __restrict__ y,
                               const float* __restrict__ pw)
{
    int t = blockIdx.x;
    float w0 = pw[2 * t], w1 = pw[2 * t + 1];
    int d = threadIdx.x * 4;
    float4 a  = *reinterpret_cast<float4*>(x + (long)t*DD + d);
    float4 y0 = *reinterpret_cast<const float4*>(y + (long)(2*t)*DD + d);
    float4 y1 = *reinterpret_cast<const float4*>(y + (long)(2*t+1)*DD + d);
    a.x += w0*y0.x + w1*y1.x;
    a.y += w0*y0.y + w1*y1.y;
    a.z += w0*y0.z + w1*y1.z;
    a.w += w0*y0.w + w1*y1.w;
    *reinterpret_cast<float4*>(x + (long)t*DD + d) = a;
}

// ---------------- launch ----------------
extern "C" void kernel_launch(void* const* d_in, const int* in_sizes, int n_in,
                              void* d_out, int out_size)
{
    const int*   token_ids = (const int*)  d_in[0];
    const int*   pos_ids   = (const int*)  d_in[1];
    const float* tok_emb   = (const float*)d_in[2];
    const float* attn_norm = (const float*)d_in[3];
    const float* wq        = (const float*)d_in[4];
    const float* wk        = (const float*)d_in[5];
    const float* wv        = (const float*)d_in[6];
    const float* qn        = (const float*)d_in[7];
    const float* kn        = (const float*)d_in[8];
    const float* wo        = (const float*)d_in[9];
    const float* ffn_norm  = (const float*)d_in[10];
    const float* router_w  = (const float*)d_in[11];
    const float* gate_w    = (const float*)d_in[12];
    const float* up_w      = (const float*)d_in[13];
    const float* down_w    = (const float*)d_in[14];
    const float* fin_norm  = (const float*)d_in[15];

    float *x, *h, *q, *k, *v, *sc, *o, *gt, *up, *y, *rlog, *pw;
    int *cnt, *ptok, *ppair;
    cudaGetSymbolAddress((void**)&x,  g_x);
    cudaGetSymbolAddress((void**)&h,  g_h);
    cudaGetSymbolAddress((void**)&q,  g_q);
    cudaGetSymbolAddress((void**)&k,  g_k);
    cudaGetSymbolAddress((void**)&v,  g_v);
    cudaGetSymbolAddress((void**)&sc, g_scores);
    cudaGetSymbolAddress((void**)&o,  g_o);
    cudaGetSymbolAddress((void**)&gt, g_gate);
    cudaGetSymbolAddress((void**)&up, g_up);
    cudaGetSymbolAddress((void**)&y,  g_y);
    cudaGetSymbolAddress((void**)&rlog, g_rlog);
    cudaGetSymbolAddress((void**)&pw,   g_pairw);
    cudaGetSymbolAddress((void**)&cnt,  g_cnt);
    cudaGetSymbolAddress((void**)&ptok, g_ptok);
    cudaGetSymbolAddress((void**)&ppair,g_ppair);

    embed_kernel<<<TT, 256>>>(token_ids, tok_emb, x);

    for (int l = 0; l < LL; l++) {
        // ---- attention ----
        rmsnorm_kernel<<<TT, 256>>>(x, attn_norm + (long)l*DD, h);
        qkv_gemm<<<dim3(12, TT/BM), 256>>>(h, wq + (long)l*DD*QD, wk + (long)l*DD*KD,
                                           wv + (long)l*DD*KD, q, k, v);
        qk_rope_fused_kernel<<<TT*(HH+KVH)/8, 256>>>(q, k, qn + (long)l*HDIM,
                                                     kn + (long)l*HDIM, pos_ids);
        attn_scores_mma<<<dim3(SS/BN, SS/BM, BB*HH), 256>>>(q, k, sc);
        softmax_kernel<<<dim3(SS, BB*HH), 256>>>(sc);
        attn_pv_mma<<<dim3(1, SS/BM, BB*HH), 256>>>(sc, v, o);
        mma_gemm<false,true><<<dim3(DD/BN, TT/BM), 256>>>(o, wo + (long)l*QD*DD, x, TT, DD, QD, QD, DD, DD);

        // ---- MoE FFN ----
        rmsnorm_kernel<<<TT, 256>>>(x, ffn_norm + (long)l*DD, h);
        router_kernel<<<TT, 256>>>(h, router_w + (long)l*DD*EE, rlog);
        cudaMemsetAsync(cnt, 0, EE * sizeof(int));
        assign_kernel<<<TT/256, 256>>>(rlog, cnt, ptok, ppair, pw);
        moe_mma_gemm<<<dim3(FF/BN, 2*TT/BM, EE), 256>>>(
            h, gate_w + (long)l*EE*DD*FF, (long)DD*FF, gt, FF, DD, DD, FF, FF, ptok, ppair, cnt);
        moe_mma_gemm<<<dim3(FF/BN, 2*TT/BM, EE), 256>>>(
            h, up_w + (long)l*EE*DD*FF, (long)DD*FF, up, FF, DD, DD, FF, FF, ptok, ppair, cnt);
        silu_mul_kernel<<<(2*TT*FF)/256, 256>>>(gt, up);
        moe_mma_gemm<<<dim3(DD/BN, 2*TT/BM, EE), 256>>>(
            gt, down_w + (long)l*EE*FF*DD, (long)FF*DD, y, DD, FF, FF, DD, DD, ppair, ppair, cnt);
        combine_kernel<<<TT, 256>>>(x, y, pw);
    }

    // ---- final norm + tied lm_head ----
    rmsnorm_kernel<<<TT, 256>>>(x, fin_norm, h);
    mma_gemm<true,false><<<dim3(VV/BN, TT/BM), 256>>>(
        h, tok_emb, (float*)d_out, TT, VV, DD, DD, DD, VV);
}